// round 2
// baseline (speedup 1.0000x reference)
#include <cuda_runtime.h>
#include <cstdint>

#define Bdim  4
#define Sdim  1024
#define Hdim  1024
#define ENTn  16
#define INNER 64
#define NOUT  2048
#define NEGC  1.0e12f

// Scratch (allocation-free rule: __device__ globals)
__device__ float g_Q[Bdim*ENTn*Sdim*INNER];   // [b][h][s][d]
__device__ float g_K[Bdim*ENTn*Sdim*INNER];
__device__ float g_sin[Sdim*(INNER/2)];       // [s][j]
__device__ float g_cos[Sdim*(INNER/2)];

__device__ __forceinline__ uint32_t f2tf(float x){
    uint32_t u; asm("cvt.rna.tf32.f32 %0, %1;" : "=r"(u) : "f"(x)); return u;
}
__device__ __forceinline__ void cp16(void* s, const void* g){
    uint32_t sa = (uint32_t)__cvta_generic_to_shared(s);
    asm volatile("cp.async.cg.shared.global [%0], [%1], 16;" :: "r"(sa), "l"(g));
}
__device__ __forceinline__ void cp_commit(){ asm volatile("cp.async.commit_group;" ::: "memory"); }
template<int N> __device__ __forceinline__ void cp_wait(){
    asm volatile("cp.async.wait_group %0;" :: "n"(N) : "memory");
}
__device__ __forceinline__ void mma_tf32(float* c, const uint32_t* a, const uint32_t* b){
    asm volatile("mma.sync.aligned.m16n8k8.row.col.f32.tf32.tf32.f32 "
        "{%0,%1,%2,%3}, {%4,%5,%6,%7}, {%8,%9}, {%0,%1,%2,%3};"
        : "+f"(c[0]), "+f"(c[1]), "+f"(c[2]), "+f"(c[3])
        : "r"(a[0]), "r"(a[1]), "r"(a[2]), "r"(a[3]), "r"(b[0]), "r"(b[1]));
}

// ---------------------------------------------------------------------------
// Kernel T: RoPE sin/cos table, matching jax fp32 math:
// freq = 10000^(-2j/64) = 10000^(-j/32); ang = s*freq; sin/cos fp32.
// ---------------------------------------------------------------------------
__global__ void sincos_kernel(){
    int idx = blockIdx.x*blockDim.x + threadIdx.x;
    if (idx >= Sdim*32) return;
    int s = idx >> 5, j = idx & 31;
    float freq = powf(10000.0f, -(float)j * 0.03125f);
    float ang  = (float)s * freq;
    g_sin[idx] = sinf(ang);
    g_cos[idx] = cosf(ang);
}

// ---------------------------------------------------------------------------
// Kernel A: C = X@W + b, fused interleaved RoPE, scatter to g_Q/g_K.
// M=4096, N=2048, K=1024. CTA tile 128x64, BK=32, tf32 mma.sync, cp.async x2.
// SMEM strides chosen for conflict-free fragment LDS:
//   As [128][36]: bank = (36m+k)%32 = (4m+k)%32  -> bijective over (m:8, k:4)
//   Bs [32][72] : bank = (72k+n)%32 = (8k+n)%32  -> bijective over (k:4, n:8)
// ---------------------------------------------------------------------------
#define A_STR 36
#define B_STR 72
#define SMEM_A_BYTES ((2*128*A_STR + 2*32*B_STR)*4)

__global__ void __launch_bounds__(256) gemm1_rope_kernel(
    const float* __restrict__ X, const float* __restrict__ W,
    const float* __restrict__ bias)
{
    extern __shared__ float sm[];
    float* As = sm;                   // [2][128][A_STR]
    float* Bs = sm + 2*128*A_STR;     // [2][32][B_STR]
    const int tid  = threadIdx.x;
    const int lane = tid & 31, warp = tid >> 5;
    const int g = lane >> 2, tg = lane & 3;
    const int wm = warp >> 1, wn = warp & 1;
    const int mtile = blockIdx.y, ntile = blockIdx.x;
    const float* Xb = X + (size_t)mtile*128*Hdim;
    const float* Wb = W + ntile*64;

    float acc[2][4][4];
    #pragma unroll
    for (int a=0;a<2;a++)
        #pragma unroll
        for (int bq=0;bq<4;bq++)
            #pragma unroll
            for (int k=0;k<4;k++) acc[a][bq][k]=0.f;

    auto load_stage = [&](int ks, int bufsel){
        float* Ad = As + bufsel*128*A_STR;
        const int k0 = ks*32;
        #pragma unroll
        for (int i=0;i<4;i++){
            int t = tid + i*256;                 // 0..1023
            int row = t >> 3, kc = (t & 7) << 2; // 128 rows x 8 chunks
            cp16(Ad + row*A_STR + kc, Xb + (size_t)row*Hdim + k0 + kc);
        }
        float* Bd = Bs + bufsel*32*B_STR;
        #pragma unroll
        for (int i=0;i<2;i++){
            int t = tid + i*256;                  // 0..511
            int kr = t >> 4, nc = (t & 15) << 2;  // 32 rows x 16 chunks
            cp16(Bd + kr*B_STR + nc, Wb + (size_t)(k0+kr)*NOUT + nc);
        }
        cp_commit();
    };

    load_stage(0, 0);
    int buf = 0;
    for (int ks = 0; ks < 32; ks++){
        if (ks < 31){ load_stage(ks+1, buf^1); cp_wait<1>(); }
        else        { cp_wait<0>(); }
        __syncthreads();
        const float* Ab = As + buf*128*A_STR;
        const float* Bb = Bs + buf*32*B_STR;
        #pragma unroll
        for (int kk=0; kk<4; kk++){
            const int k0 = kk*8;
            uint32_t af[2][4], bf[4][2];
            #pragma unroll
            for (int mt=0; mt<2; mt++){
                int rb = wm*32 + mt*16;
                af[mt][0] = f2tf(Ab[(rb+g  )*A_STR + k0+tg  ]);
                af[mt][1] = f2tf(Ab[(rb+g+8)*A_STR + k0+tg  ]);
                af[mt][2] = f2tf(Ab[(rb+g  )*A_STR + k0+tg+4]);
                af[mt][3] = f2tf(Ab[(rb+g+8)*A_STR + k0+tg+4]);
            }
            #pragma unroll
            for (int nt=0; nt<4; nt++){
                int nb = wn*32 + nt*8 + g;
                bf[nt][0] = f2tf(Bb[(k0+tg  )*B_STR + nb]);
                bf[nt][1] = f2tf(Bb[(k0+tg+4)*B_STR + nb]);
            }
            #pragma unroll
            for (int mt=0; mt<2; mt++)
                #pragma unroll
                for (int nt=0; nt<4; nt++)
                    mma_tf32(acc[mt][nt], af[mt], bf[nt]);
        }
        __syncthreads();
        buf ^= 1;
    }

    // Epilogue: bias + RoPE (interleaved pairs are exactly the c0/c1 accum pair)
    #pragma unroll
    for (int nt=0; nt<4; nt++){
        const int n_loc = wn*32 + nt*8 + 2*tg;
        const int c = ntile*64 + n_loc;          // even
        const int h = c >> 7, r = c & 127;
        const int d = r & 63, jj = d >> 1;
        float* dst = (r < 64) ? g_Q : g_K;
        const float b0 = bias[c], b1 = bias[c+1];
        #pragma unroll
        for (int mt=0; mt<2; mt++){
            #pragma unroll
            for (int p=0; p<2; p++){
                int m = mtile*128 + wm*32 + mt*16 + g + p*8;
                int bb = m >> 10, s = m & 1023;
                float sv = g_sin[s*32 + jj], cv = g_cos[s*32 + jj];
                float v0 = acc[mt][nt][2*p]   + b0;
                float v1 = acc[mt][nt][2*p+1] + b1;
                float o0 = v0*cv - v1*sv;
                float o1 = v1*cv + v0*sv;
                int idx = ((bb*ENTn + h)*Sdim + s)*INNER + d;
                *reinterpret_cast<float2*>(dst + idx) = make_float2(o0, o1);
            }
        }
    }
}

// ---------------------------------------------------------------------------
// Kernel B: logits[z=(b,h)][m][n] = (Q[m]·K[n]) masked/scaled.
// Grid (ntile, mtile, z). 128x128 tiles.
// Strictly-lower tiles: exact constant, pure float4 streaming stores.
// Upper/diagonal: tf32 mma over d=64, pad/tril epilogue.
// ---------------------------------------------------------------------------
#define QK_STR 68
#define SMEM_B_BYTES (2*128*QK_STR*4)

__global__ void __launch_bounds__(256) attn_logits_kernel(
    const float* __restrict__ tok, float* __restrict__ out)
{
    const int ntile = blockIdx.x, mtile = blockIdx.y, z = blockIdx.z;
    const int bidx = z >> 4;
    const int tid = threadIdx.x;
    float* outb = out + ((size_t)z << 20);
    const float* padp = tok + bidx*Sdim + ntile*128;

    if (ntile < mtile){
        // fully-masked tile: value = (-(1-pad)*NEG - NEG)/8, exact vs reference
        const int n4 = (tid & 31) << 2;
        const int m0 = mtile*128 + (tid >> 5);
        float4 pv = *reinterpret_cast<const float4*>(padp + n4);
        float4 val;
        val.x = (-(1.0f - pv.x)*NEGC - NEGC)*0.125f;
        val.y = (-(1.0f - pv.y)*NEGC - NEGC)*0.125f;
        val.z = (-(1.0f - pv.z)*NEGC - NEGC)*0.125f;
        val.w = (-(1.0f - pv.w)*NEGC - NEGC)*0.125f;
        const int ncol = ntile*128 + n4;
        #pragma unroll
        for (int i=0;i<16;i++)
            *reinterpret_cast<float4*>(outb + ((size_t)(m0 + i*8) << 10) + ncol) = val;
        return;
    }

    extern __shared__ float sm[];
    float* Qs = sm;                // [128][QK_STR]
    float* Ks = sm + 128*QK_STR;   // [128][QK_STR]
    __shared__ float pad_s[128];
    if (tid < 128) pad_s[tid] = padp[tid];

    const float* Qg = g_Q + ((size_t)z*Sdim + (size_t)mtile*128)*INNER;
    const float* Kg = g_K + ((size_t)z*Sdim + (size_t)ntile*128)*INNER;
    #pragma unroll
    for (int i=0;i<8;i++){
        int t = tid + i*256;                   // 0..2047
        int row = t >> 4, ch = (t & 15) << 2;  // 128 rows x 16 chunks
        cp16(Qs + row*QK_STR + ch, Qg + row*INNER + ch);
        cp16(Ks + row*QK_STR + ch, Kg + row*INNER + ch);
    }
    cp_commit();
    cp_wait<0>();
    __syncthreads();

    const int lane = tid & 31, warp = tid >> 5;
    const int g = lane >> 2, tg = lane & 3;
    const int wm = warp >> 1, wn = warp & 1;   // 4 x 2 warps, warp tile 32x64

    float acc[2][8][4];
    #pragma unroll
    for (int a=0;a<2;a++)
        #pragma unroll
        for (int bq=0;bq<8;bq++)
            #pragma unroll
            for (int k=0;k<4;k++) acc[a][bq][k]=0.f;

    #pragma unroll
    for (int kk=0; kk<8; kk++){
        const int k0 = kk*8;
        uint32_t af[2][4], bf[8][2];
        #pragma unroll
        for (int mt=0; mt<2; mt++){
            int rb = wm*32 + mt*16;
            af[mt][0] = f2tf(Qs[(rb+g  )*QK_STR + k0+tg  ]);
            af[mt][1] = f2tf(Qs[(rb+g+8)*QK_STR + k0+tg  ]);
            af[mt][2] = f2tf(Qs[(rb+g  )*QK_STR + k0+tg+4]);
            af[mt][3] = f2tf(Qs[(rb+g+8)*QK_STR + k0+tg+4]);
        }
        #pragma unroll
        for (int nt=0; nt<8; nt++){
            int nb = wn*64 + nt*8 + g;
            bf[nt][0] = f2tf(Ks[nb*QK_STR + k0+tg  ]);
            bf[nt][1] = f2tf(Ks[nb*QK_STR + k0+tg+4]);
        }
        #pragma unroll
        for (int mt=0; mt<2; mt++)
            #pragma unroll
            for (int nt=0; nt<8; nt++)
                mma_tf32(acc[mt][nt], af[mt], bf[nt]);
    }

    #pragma unroll
    for (int mt=0; mt<2; mt++){
        #pragma unroll
        for (int nt=0; nt<8; nt++){
            const int n_loc = wn*64 + nt*8 + 2*tg;
            const int n = ntile*128 + n_loc;
            const float p0 = pad_s[n_loc], p1 = pad_s[n_loc+1];
            #pragma unroll
            for (int p=0; p<2; p++){
                const int m = mtile*128 + wm*32 + mt*16 + g + p*8;
                float v0 = acc[mt][nt][2*p]   * p0 - (1.0f - p0)*NEGC - ((n   < m) ? NEGC : 0.0f);
                float v1 = acc[mt][nt][2*p+1] * p1 - (1.0f - p1)*NEGC - ((n+1 < m) ? NEGC : 0.0f);
                *reinterpret_cast<float2*>(outb + ((size_t)m << 10) + n) =
                    make_float2(v0*0.125f, v1*0.125f);
            }
        }
    }
}

// ---------------------------------------------------------------------------
extern "C" void kernel_launch(void* const* d_in, const int* in_sizes, int n_in,
                              void* d_out, int out_size)
{
    const float* X    = (const float*)d_in[0];
    const float* W    = (const float*)d_in[1];
    const float* bias = (const float*)d_in[2];
    const float* tok  = (const float*)d_in[3];
    float* out = (float*)d_out;

    cudaFuncSetAttribute(gemm1_rope_kernel,
        cudaFuncAttributeMaxDynamicSharedMemorySize, SMEM_A_BYTES);
    cudaFuncSetAttribute(attn_logits_kernel,
        cudaFuncAttributeMaxDynamicSharedMemorySize, SMEM_B_BYTES);

    sincos_kernel<<<64, 512>>>();
    gemm1_rope_kernel<<<dim3(32, 32), 256, SMEM_A_BYTES>>>(X, W, bias);
    attn_logits_kernel<<<dim3(8, 8, 64), 256, SMEM_B_BYTES>>>(tok, out);
}

// round 3
// speedup vs baseline: 1.0005x; 1.0005x over previous
#include <cuda_runtime.h>
#include <cstdint>

#define Bdim  4
#define Sdim  1024
#define Hdim  1024
#define ENTn  16
#define INNER 64
#define NOUT  2048
#define NEGC  1.0e12f

// Scratch (allocation-free rule: __device__ globals)
__device__ float g_Q[Bdim*ENTn*Sdim*INNER];   // [b][h][s][d]
__device__ float g_K[Bdim*ENTn*Sdim*INNER];
__device__ float g_sin[Sdim*(INNER/2)];       // [s][j]
__device__ float g_cos[Sdim*(INNER/2)];

__device__ __forceinline__ uint32_t f2tf(float x){
    uint32_t u; asm("cvt.rna.tf32.f32 %0, %1;" : "=r"(u) : "f"(x)); return u;
}
__device__ __forceinline__ void cp16(void* s, const void* g){
    uint32_t sa = (uint32_t)__cvta_generic_to_shared(s);
    asm volatile("cp.async.cg.shared.global [%0], [%1], 16;" :: "r"(sa), "l"(g));
}
__device__ __forceinline__ void cp_commit(){ asm volatile("cp.async.commit_group;" ::: "memory"); }
template<int N> __device__ __forceinline__ void cp_wait(){
    asm volatile("cp.async.wait_group %0;" :: "n"(N) : "memory");
}
__device__ __forceinline__ void mma_tf32(float* c, const uint32_t* a, const uint32_t* b){
    asm volatile("mma.sync.aligned.m16n8k8.row.col.f32.tf32.tf32.f32 "
        "{%0,%1,%2,%3}, {%4,%5,%6,%7}, {%8,%9}, {%0,%1,%2,%3};"
        : "+f"(c[0]), "+f"(c[1]), "+f"(c[2]), "+f"(c[3])
        : "r"(a[0]), "r"(a[1]), "r"(a[2]), "r"(a[3]), "r"(b[0]), "r"(b[1]));
}

// ---------------------------------------------------------------------------
// Kernel T: RoPE sin/cos table, matching jax fp32 math:
// freq = 10000^(-2j/64) = 10000^(-j/32); ang = s*freq; sin/cos fp32.
// ---------------------------------------------------------------------------
__global__ void sincos_kernel(){
    int idx = blockIdx.x*blockDim.x + threadIdx.x;
    if (idx >= Sdim*32) return;
    int s = idx >> 5, j = idx & 31;
    float freq = powf(10000.0f, -(float)j * 0.03125f);
    float ang  = (float)s * freq;
    g_sin[idx] = sinf(ang);
    g_cos[idx] = cosf(ang);
}

// ---------------------------------------------------------------------------
// Kernel A: C = X@W + b, fused interleaved RoPE, scatter to g_Q/g_K.
// M=4096, N=2048, K=1024. CTA tile 128x64, BK=32, tf32 mma.sync, cp.async x2.
// SMEM strides chosen for conflict-free fragment LDS:
//   As [128][36]: bank = (36m+k)%32 = (4m+k)%32  -> bijective over (m:8, k:4)
//   Bs [32][72] : bank = (72k+n)%32 = (8k+n)%32  -> bijective over (k:4, n:8)
// ---------------------------------------------------------------------------
#define A_STR 36
#define B_STR 72
#define SMEM_A_BYTES ((2*128*A_STR + 2*32*B_STR)*4)

__global__ void __launch_bounds__(256) gemm1_rope_kernel(
    const float* __restrict__ X, const float* __restrict__ W,
    const float* __restrict__ bias)
{
    extern __shared__ float sm[];
    float* As = sm;                   // [2][128][A_STR]
    float* Bs = sm + 2*128*A_STR;     // [2][32][B_STR]
    const int tid  = threadIdx.x;
    const int lane = tid & 31, warp = tid >> 5;
    const int g = lane >> 2, tg = lane & 3;
    const int wm = warp >> 1, wn = warp & 1;
    const int mtile = blockIdx.y, ntile = blockIdx.x;
    const float* Xb = X + (size_t)mtile*128*Hdim;
    const float* Wb = W + ntile*64;

    float acc[2][4][4];
    #pragma unroll
    for (int a=0;a<2;a++)
        #pragma unroll
        for (int bq=0;bq<4;bq++)
            #pragma unroll
            for (int k=0;k<4;k++) acc[a][bq][k]=0.f;

    auto load_stage = [&](int ks, int bufsel){
        float* Ad = As + bufsel*128*A_STR;
        const int k0 = ks*32;
        #pragma unroll
        for (int i=0;i<4;i++){
            int t = tid + i*256;                 // 0..1023
            int row = t >> 3, kc = (t & 7) << 2; // 128 rows x 8 chunks
            cp16(Ad + row*A_STR + kc, Xb + (size_t)row*Hdim + k0 + kc);
        }
        float* Bd = Bs + bufsel*32*B_STR;
        #pragma unroll
        for (int i=0;i<2;i++){
            int t = tid + i*256;                  // 0..511
            int kr = t >> 4, nc = (t & 15) << 2;  // 32 rows x 16 chunks
            cp16(Bd + kr*B_STR + nc, Wb + (size_t)(k0+kr)*NOUT + nc);
        }
        cp_commit();
    };

    load_stage(0, 0);
    int buf = 0;
    for (int ks = 0; ks < 32; ks++){
        if (ks < 31){ load_stage(ks+1, buf^1); cp_wait<1>(); }
        else        { cp_wait<0>(); }
        __syncthreads();
        const float* Ab = As + buf*128*A_STR;
        const float* Bb = Bs + buf*32*B_STR;
        #pragma unroll
        for (int kk=0; kk<4; kk++){
            const int k0 = kk*8;
            uint32_t af[2][4], bf[4][2];
            #pragma unroll
            for (int mt=0; mt<2; mt++){
                int rb = wm*32 + mt*16;
                af[mt][0] = f2tf(Ab[(rb+g  )*A_STR + k0+tg  ]);
                af[mt][1] = f2tf(Ab[(rb+g+8)*A_STR + k0+tg  ]);
                af[mt][2] = f2tf(Ab[(rb+g  )*A_STR + k0+tg+4]);
                af[mt][3] = f2tf(Ab[(rb+g+8)*A_STR + k0+tg+4]);
            }
            #pragma unroll
            for (int nt=0; nt<4; nt++){
                int nb = wn*32 + nt*8 + g;
                bf[nt][0] = f2tf(Bb[(k0+tg  )*B_STR + nb]);
                bf[nt][1] = f2tf(Bb[(k0+tg+4)*B_STR + nb]);
            }
            #pragma unroll
            for (int mt=0; mt<2; mt++)
                #pragma unroll
                for (int nt=0; nt<4; nt++)
                    mma_tf32(acc[mt][nt], af[mt], bf[nt]);
        }
        __syncthreads();
        buf ^= 1;
    }

    // Epilogue: bias + RoPE (interleaved pairs are exactly the c0/c1 accum pair)
    #pragma unroll
    for (int nt=0; nt<4; nt++){
        const int n_loc = wn*32 + nt*8 + 2*tg;
        const int c = ntile*64 + n_loc;          // even
        const int h = c >> 7, r = c & 127;
        const int d = r & 63, jj = d >> 1;
        float* dst = (r < 64) ? g_Q : g_K;
        const float b0 = bias[c], b1 = bias[c+1];
        #pragma unroll
        for (int mt=0; mt<2; mt++){
            #pragma unroll
            for (int p=0; p<2; p++){
                int m = mtile*128 + wm*32 + mt*16 + g + p*8;
                int bb = m >> 10, s = m & 1023;
                float sv = g_sin[s*32 + jj], cv = g_cos[s*32 + jj];
                float v0 = acc[mt][nt][2*p]   + b0;
                float v1 = acc[mt][nt][2*p+1] + b1;
                float o0 = v0*cv - v1*sv;
                float o1 = v1*cv + v0*sv;
                int idx = ((bb*ENTn + h)*Sdim + s)*INNER + d;
                *reinterpret_cast<float2*>(dst + idx) = make_float2(o0, o1);
            }
        }
    }
}

// ---------------------------------------------------------------------------
// Kernel B: logits[z=(b,h)][m][n] = (Q[m]·K[n]) masked/scaled.
// Grid (ntile, mtile, z). 128x128 tiles.
// Strictly-lower tiles: exact constant, pure float4 streaming stores.
// Upper/diagonal: tf32 mma over d=64, pad/tril epilogue.
// ---------------------------------------------------------------------------
#define QK_STR 68
#define SMEM_B_BYTES (2*128*QK_STR*4)

__global__ void __launch_bounds__(256) attn_logits_kernel(
    const float* __restrict__ tok, float* __restrict__ out)
{
    const int ntile = blockIdx.x, mtile = blockIdx.y, z = blockIdx.z;
    const int bidx = z >> 4;
    const int tid = threadIdx.x;
    float* outb = out + ((size_t)z << 20);
    const float* padp = tok + bidx*Sdim + ntile*128;

    if (ntile < mtile){
        // fully-masked tile: value = (-(1-pad)*NEG - NEG)/8, exact vs reference
        const int n4 = (tid & 31) << 2;
        const int m0 = mtile*128 + (tid >> 5);
        float4 pv = *reinterpret_cast<const float4*>(padp + n4);
        float4 val;
        val.x = (-(1.0f - pv.x)*NEGC - NEGC)*0.125f;
        val.y = (-(1.0f - pv.y)*NEGC - NEGC)*0.125f;
        val.z = (-(1.0f - pv.z)*NEGC - NEGC)*0.125f;
        val.w = (-(1.0f - pv.w)*NEGC - NEGC)*0.125f;
        const int ncol = ntile*128 + n4;
        #pragma unroll
        for (int i=0;i<16;i++)
            *reinterpret_cast<float4*>(outb + ((size_t)(m0 + i*8) << 10) + ncol) = val;
        return;
    }

    extern __shared__ float sm[];
    float* Qs = sm;                // [128][QK_STR]
    float* Ks = sm + 128*QK_STR;   // [128][QK_STR]
    __shared__ float pad_s[128];
    if (tid < 128) pad_s[tid] = padp[tid];

    const float* Qg = g_Q + ((size_t)z*Sdim + (size_t)mtile*128)*INNER;
    const float* Kg = g_K + ((size_t)z*Sdim + (size_t)ntile*128)*INNER;
    #pragma unroll
    for (int i=0;i<8;i++){
        int t = tid + i*256;                   // 0..2047
        int row = t >> 4, ch = (t & 15) << 2;  // 128 rows x 16 chunks
        cp16(Qs + row*QK_STR + ch, Qg + row*INNER + ch);
        cp16(Ks + row*QK_STR + ch, Kg + row*INNER + ch);
    }
    cp_commit();
    cp_wait<0>();
    __syncthreads();

    const int lane = tid & 31, warp = tid >> 5;
    const int g = lane >> 2, tg = lane & 3;
    const int wm = warp >> 1, wn = warp & 1;   // 4 x 2 warps, warp tile 32x64

    float acc[2][8][4];
    #pragma unroll
    for (int a=0;a<2;a++)
        #pragma unroll
        for (int bq=0;bq<8;bq++)
            #pragma unroll
            for (int k=0;k<4;k++) acc[a][bq][k]=0.f;

    #pragma unroll
    for (int kk=0; kk<8; kk++){
        const int k0 = kk*8;
        uint32_t af[2][4], bf[8][2];
        #pragma unroll
        for (int mt=0; mt<2; mt++){
            int rb = wm*32 + mt*16;
            af[mt][0] = f2tf(Qs[(rb+g  )*QK_STR + k0+tg  ]);
            af[mt][1] = f2tf(Qs[(rb+g+8)*QK_STR + k0+tg  ]);
            af[mt][2] = f2tf(Qs[(rb+g  )*QK_STR + k0+tg+4]);
            af[mt][3] = f2tf(Qs[(rb+g+8)*QK_STR + k0+tg+4]);
        }
        #pragma unroll
        for (int nt=0; nt<8; nt++){
            int nb = wn*64 + nt*8 + g;
            bf[nt][0] = f2tf(Ks[nb*QK_STR + k0+tg  ]);
            bf[nt][1] = f2tf(Ks[nb*QK_STR + k0+tg+4]);
        }
        #pragma unroll
        for (int mt=0; mt<2; mt++)
            #pragma unroll
            for (int nt=0; nt<8; nt++)
                mma_tf32(acc[mt][nt], af[mt], bf[nt]);
    }

    #pragma unroll
    for (int mt=0; mt<2; mt++){
        #pragma unroll
        for (int nt=0; nt<8; nt++){
            const int n_loc = wn*64 + nt*8 + 2*tg;
            const int n = ntile*128 + n_loc;
            const float p0 = pad_s[n_loc], p1 = pad_s[n_loc+1];
            #pragma unroll
            for (int p=0; p<2; p++){
                const int m = mtile*128 + wm*32 + mt*16 + g + p*8;
                float v0 = acc[mt][nt][2*p]   * p0 - (1.0f - p0)*NEGC - ((n   < m) ? NEGC : 0.0f);
                float v1 = acc[mt][nt][2*p+1] * p1 - (1.0f - p1)*NEGC - ((n+1 < m) ? NEGC : 0.0f);
                *reinterpret_cast<float2*>(outb + ((size_t)m << 10) + n) =
                    make_float2(v0*0.125f, v1*0.125f);
            }
        }
    }
}

// ---------------------------------------------------------------------------
extern "C" void kernel_launch(void* const* d_in, const int* in_sizes, int n_in,
                              void* d_out, int out_size)
{
    const float* X    = (const float*)d_in[0];
    const float* W    = (const float*)d_in[1];
    const float* bias = (const float*)d_in[2];
    const float* tok  = (const float*)d_in[3];
    float* out = (float*)d_out;

    cudaFuncSetAttribute(gemm1_rope_kernel,
        cudaFuncAttributeMaxDynamicSharedMemorySize, SMEM_A_BYTES);
    cudaFuncSetAttribute(attn_logits_kernel,
        cudaFuncAttributeMaxDynamicSharedMemorySize, SMEM_B_BYTES);

    sincos_kernel<<<64, 512>>>();
    gemm1_rope_kernel<<<dim3(32, 32), 256, SMEM_A_BYTES>>>(X, W, bias);
    attn_logits_kernel<<<dim3(8, 8, 64), 256, SMEM_B_BYTES>>>(tok, out);
}

// round 4
// speedup vs baseline: 1.0049x; 1.0045x over previous
#include <cuda_runtime.h>
#include <cstdint>

#define Bdim  4
#define Sdim  1024
#define Hdim  1024
#define ENTn  16
#define INNER 64
#define NOUT  2048
#define NEGC  1.0e12f

// Scratch (allocation-free rule: __device__ globals)
__device__ float g_Q[Bdim*ENTn*Sdim*INNER];   // [b][h][s][d]
__device__ float g_K[Bdim*ENTn*Sdim*INNER];
__device__ float g_sin[Sdim*(INNER/2)];       // [s][j]
__device__ float g_cos[Sdim*(INNER/2)];

__device__ __forceinline__ uint32_t f2tf(float x){
    uint32_t u; asm("cvt.rna.tf32.f32 %0, %1;" : "=r"(u) : "f"(x)); return u;
}
__device__ __forceinline__ void cp16(void* s, const void* g){
    uint32_t sa = (uint32_t)__cvta_generic_to_shared(s);
    asm volatile("cp.async.cg.shared.global [%0], [%1], 16;" :: "r"(sa), "l"(g));
}
__device__ __forceinline__ void cp_commit(){ asm volatile("cp.async.commit_group;" ::: "memory"); }
template<int N> __device__ __forceinline__ void cp_wait(){
    asm volatile("cp.async.wait_group %0;" :: "n"(N) : "memory");
}
__device__ __forceinline__ void mma_tf32(float* c, const uint32_t* a, const uint32_t* b){
    asm volatile("mma.sync.aligned.m16n8k8.row.col.f32.tf32.tf32.f32 "
        "{%0,%1,%2,%3}, {%4,%5,%6,%7}, {%8,%9}, {%0,%1,%2,%3};"
        : "+f"(c[0]), "+f"(c[1]), "+f"(c[2]), "+f"(c[3])
        : "r"(a[0]), "r"(a[1]), "r"(a[2]), "r"(a[3]), "r"(b[0]), "r"(b[1]));
}

// ---------------------------------------------------------------------------
// Kernel T: RoPE sin/cos table, matching jax fp32 math:
// freq = 10000^(-2j/64) = 10000^(-j/32); ang = s*freq; sin/cos fp32.
// ---------------------------------------------------------------------------
__global__ void sincos_kernel(){
    int idx = blockIdx.x*blockDim.x + threadIdx.x;
    if (idx >= Sdim*32) return;
    int s = idx >> 5, j = idx & 31;
    float freq = powf(10000.0f, -(float)j * 0.03125f);
    float ang  = (float)s * freq;
    g_sin[idx] = sinf(ang);
    g_cos[idx] = cosf(ang);
}

// ---------------------------------------------------------------------------
// Kernel A: C = X@W + b, fused interleaved RoPE, scatter to g_Q/g_K.
// M=4096, N=2048, K=1024. CTA tile 128x64, BK=32, tf32 mma.sync, cp.async x2.
// SMEM strides chosen for conflict-free fragment LDS:
//   As [128][36]: bank = (36m+k)%32 = (4m+k)%32  -> bijective over (m:8, k:4)
//   Bs [32][72] : bank = (72k+n)%32 = (8k+n)%32  -> bijective over (k:4, n:8)
// ---------------------------------------------------------------------------
#define A_STR 36
#define B_STR 72
#define SMEM_A_BYTES ((2*128*A_STR + 2*32*B_STR)*4)

__global__ void __launch_bounds__(256) gemm1_rope_kernel(
    const float* __restrict__ X, const float* __restrict__ W,
    const float* __restrict__ bias)
{
    extern __shared__ float sm[];
    float* As = sm;                   // [2][128][A_STR]
    float* Bs = sm + 2*128*A_STR;     // [2][32][B_STR]
    const int tid  = threadIdx.x;
    const int lane = tid & 31, warp = tid >> 5;
    const int g = lane >> 2, tg = lane & 3;
    const int wm = warp >> 1, wn = warp & 1;
    const int mtile = blockIdx.y, ntile = blockIdx.x;
    const float* Xb = X + (size_t)mtile*128*Hdim;
    const float* Wb = W + ntile*64;

    float acc[2][4][4];
    #pragma unroll
    for (int a=0;a<2;a++)
        #pragma unroll
        for (int bq=0;bq<4;bq++)
            #pragma unroll
            for (int k=0;k<4;k++) acc[a][bq][k]=0.f;

    auto load_stage = [&](int ks, int bufsel){
        float* Ad = As + bufsel*128*A_STR;
        const int k0 = ks*32;
        #pragma unroll
        for (int i=0;i<4;i++){
            int t = tid + i*256;                 // 0..1023
            int row = t >> 3, kc = (t & 7) << 2; // 128 rows x 8 chunks
            cp16(Ad + row*A_STR + kc, Xb + (size_t)row*Hdim + k0 + kc);
        }
        float* Bd = Bs + bufsel*32*B_STR;
        #pragma unroll
        for (int i=0;i<2;i++){
            int t = tid + i*256;                  // 0..511
            int kr = t >> 4, nc = (t & 15) << 2;  // 32 rows x 16 chunks
            cp16(Bd + kr*B_STR + nc, Wb + (size_t)(k0+kr)*NOUT + nc);
        }
        cp_commit();
    };

    load_stage(0, 0);
    int buf = 0;
    for (int ks = 0; ks < 32; ks++){
        if (ks < 31){ load_stage(ks+1, buf^1); cp_wait<1>(); }
        else        { cp_wait<0>(); }
        __syncthreads();
        const float* Ab = As + buf*128*A_STR;
        const float* Bb = Bs + buf*32*B_STR;
        #pragma unroll
        for (int kk=0; kk<4; kk++){
            const int k0 = kk*8;
            uint32_t af[2][4], bf[4][2];
            #pragma unroll
            for (int mt=0; mt<2; mt++){
                int rb = wm*32 + mt*16;
                af[mt][0] = f2tf(Ab[(rb+g  )*A_STR + k0+tg  ]);
                af[mt][1] = f2tf(Ab[(rb+g+8)*A_STR + k0+tg  ]);
                af[mt][2] = f2tf(Ab[(rb+g  )*A_STR + k0+tg+4]);
                af[mt][3] = f2tf(Ab[(rb+g+8)*A_STR + k0+tg+4]);
            }
            #pragma unroll
            for (int nt=0; nt<4; nt++){
                int nb = wn*32 + nt*8 + g;
                bf[nt][0] = f2tf(Bb[(k0+tg  )*B_STR + nb]);
                bf[nt][1] = f2tf(Bb[(k0+tg+4)*B_STR + nb]);
            }
            #pragma unroll
            for (int mt=0; mt<2; mt++)
                #pragma unroll
                for (int nt=0; nt<4; nt++)
                    mma_tf32(acc[mt][nt], af[mt], bf[nt]);
        }
        __syncthreads();
        buf ^= 1;
    }

    // Epilogue: bias + RoPE (interleaved pairs are exactly the c0/c1 accum pair)
    #pragma unroll
    for (int nt=0; nt<4; nt++){
        const int n_loc = wn*32 + nt*8 + 2*tg;
        const int c = ntile*64 + n_loc;          // even
        const int h = c >> 7, r = c & 127;
        const int d = r & 63, jj = d >> 1;
        float* dst = (r < 64) ? g_Q : g_K;
        const float b0 = bias[c], b1 = bias[c+1];
        #pragma unroll
        for (int mt=0; mt<2; mt++){
            #pragma unroll
            for (int p=0; p<2; p++){
                int m = mtile*128 + wm*32 + mt*16 + g + p*8;
                int bb = m >> 10, s = m & 1023;
                float sv = g_sin[s*32 + jj], cv = g_cos[s*32 + jj];
                float v0 = acc[mt][nt][2*p]   + b0;
                float v1 = acc[mt][nt][2*p+1] + b1;
                float o0 = v0*cv - v1*sv;
                float o1 = v1*cv + v0*sv;
                int idx = ((bb*ENTn + h)*Sdim + s)*INNER + d;
                *reinterpret_cast<float2*>(dst + idx) = make_float2(o0, o1);
            }
        }
    }
}

// ---------------------------------------------------------------------------
// Kernel B: logits[z=(b,h)][m][n] = (Q[m]·K[n]) masked/scaled.
// Grid (ntile, mtile, z). 128x128 tiles.
// Strictly-lower tiles: exact constant, pure float4 streaming stores.
// Upper/diagonal: tf32 mma over d=64, pad/tril epilogue.
// ---------------------------------------------------------------------------
#define QK_STR 68
#define SMEM_B_BYTES (2*128*QK_STR*4)

__global__ void __launch_bounds__(256) attn_logits_kernel(
    const float* __restrict__ tok, float* __restrict__ out)
{
    const int ntile = blockIdx.x, mtile = blockIdx.y, z = blockIdx.z;
    const int bidx = z >> 4;
    const int tid = threadIdx.x;
    float* outb = out + ((size_t)z << 20);
    const float* padp = tok + bidx*Sdim + ntile*128;

    if (ntile < mtile){
        // fully-masked tile: value = (-(1-pad)*NEG - NEG)/8, exact vs reference
        const int n4 = (tid & 31) << 2;
        const int m0 = mtile*128 + (tid >> 5);
        float4 pv = *reinterpret_cast<const float4*>(padp + n4);
        float4 val;
        val.x = (-(1.0f - pv.x)*NEGC - NEGC)*0.125f;
        val.y = (-(1.0f - pv.y)*NEGC - NEGC)*0.125f;
        val.z = (-(1.0f - pv.z)*NEGC - NEGC)*0.125f;
        val.w = (-(1.0f - pv.w)*NEGC - NEGC)*0.125f;
        const int ncol = ntile*128 + n4;
        #pragma unroll
        for (int i=0;i<16;i++)
            *reinterpret_cast<float4*>(outb + ((size_t)(m0 + i*8) << 10) + ncol) = val;
        return;
    }

    extern __shared__ float sm[];
    float* Qs = sm;                // [128][QK_STR]
    float* Ks = sm + 128*QK_STR;   // [128][QK_STR]
    __shared__ float pad_s[128];
    if (tid < 128) pad_s[tid] = padp[tid];

    const float* Qg = g_Q + ((size_t)z*Sdim + (size_t)mtile*128)*INNER;
    const float* Kg = g_K + ((size_t)z*Sdim + (size_t)ntile*128)*INNER;
    #pragma unroll
    for (int i=0;i<8;i++){
        int t = tid + i*256;                   // 0..2047
        int row = t >> 4, ch = (t & 15) << 2;  // 128 rows x 16 chunks
        cp16(Qs + row*QK_STR + ch, Qg + row*INNER + ch);
        cp16(Ks + row*QK_STR + ch, Kg + row*INNER + ch);
    }
    cp_commit();
    cp_wait<0>();
    __syncthreads();

    const int lane = tid & 31, warp = tid >> 5;
    const int g = lane >> 2, tg = lane & 3;
    const int wm = warp >> 1, wn = warp & 1;   // 4 x 2 warps, warp tile 32x64

    float acc[2][8][4];
    #pragma unroll
    for (int a=0;a<2;a++)
        #pragma unroll
        for (int bq=0;bq<8;bq++)
            #pragma unroll
            for (int k=0;k<4;k++) acc[a][bq][k]=0.f;

    #pragma unroll
    for (int kk=0; kk<8; kk++){
        const int k0 = kk*8;
        uint32_t af[2][4], bf[8][2];
        #pragma unroll
        for (int mt=0; mt<2; mt++){
            int rb = wm*32 + mt*16;
            af[mt][0] = f2tf(Qs[(rb+g  )*QK_STR + k0+tg  ]);
            af[mt][1] = f2tf(Qs[(rb+g+8)*QK_STR + k0+tg  ]);
            af[mt][2] = f2tf(Qs[(rb+g  )*QK_STR + k0+tg+4]);
            af[mt][3] = f2tf(Qs[(rb+g+8)*QK_STR + k0+tg+4]);
        }
        #pragma unroll
        for (int nt=0; nt<8; nt++){
            int nb = wn*64 + nt*8 + g;
            bf[nt][0] = f2tf(Ks[nb*QK_STR + k0+tg  ]);
            bf[nt][1] = f2tf(Ks[nb*QK_STR + k0+tg+4]);
        }
        #pragma unroll
        for (int mt=0; mt<2; mt++)
            #pragma unroll
            for (int nt=0; nt<8; nt++)
                mma_tf32(acc[mt][nt], af[mt], bf[nt]);
    }

    #pragma unroll
    for (int mt=0; mt<2; mt++){
        #pragma unroll
        for (int nt=0; nt<8; nt++){
            const int n_loc = wn*64 + nt*8 + 2*tg;
            const int n = ntile*128 + n_loc;
            const float p0 = pad_s[n_loc], p1 = pad_s[n_loc+1];
            #pragma unroll
            for (int p=0; p<2; p++){
                const int m = mtile*128 + wm*32 + mt*16 + g + p*8;
                float v0 = acc[mt][nt][2*p]   * p0 - (1.0f - p0)*NEGC - ((n   < m) ? NEGC : 0.0f);
                float v1 = acc[mt][nt][2*p+1] * p1 - (1.0f - p1)*NEGC - ((n+1 < m) ? NEGC : 0.0f);
                *reinterpret_cast<float2*>(outb + ((size_t)m << 10) + n) =
                    make_float2(v0*0.125f, v1*0.125f);
            }
        }
    }
}

// ---------------------------------------------------------------------------
extern "C" void kernel_launch(void* const* d_in, const int* in_sizes, int n_in,
                              void* d_out, int out_size)
{
    const float* X    = (const float*)d_in[0];
    const float* W    = (const float*)d_in[1];
    const float* bias = (const float*)d_in[2];
    const float* tok  = (const float*)d_in[3];
    float* out = (float*)d_out;

    cudaFuncSetAttribute(gemm1_rope_kernel,
        cudaFuncAttributeMaxDynamicSharedMemorySize, SMEM_A_BYTES);
    cudaFuncSetAttribute(attn_logits_kernel,
        cudaFuncAttributeMaxDynamicSharedMemorySize, SMEM_B_BYTES);

    sincos_kernel<<<64, 512>>>();
    gemm1_rope_kernel<<<dim3(32, 32), 256, SMEM_A_BYTES>>>(X, W, bias);
    attn_logits_kernel<<<dim3(8, 8, 64), 256, SMEM_B_BYTES>>>(tok, out);
}

// round 5
// speedup vs baseline: 1.3005x; 1.2941x over previous
#include <cuda_runtime.h>
#include <cuda_bf16.h>
#include <cstdint>

#define Bdim  4
#define Sdim  1024
#define Hdim  1024
#define ENTn  16
#define INNER 64
#define NOUT  2048
#define NEGC  1.0e12f

// Scratch (allocation-free rule: __device__ globals)
__device__ __nv_bfloat16 g_Q[Bdim*ENTn*Sdim*INNER];   // [b][h][s][d] bf16
__device__ __nv_bfloat16 g_K[Bdim*ENTn*Sdim*INNER];
__device__ __nv_bfloat16 g_Xbf[Bdim*Sdim*Hdim];       // X in bf16 [m][k]
__device__ __nv_bfloat16 g_Wt[NOUT*Hdim];             // W^T in bf16 [n][k]
__device__ float g_sin[Sdim*(INNER/2)];               // [s][j]
__device__ float g_cos[Sdim*(INNER/2)];

__device__ __forceinline__ void cp16(void* s, const void* g){
    uint32_t sa = (uint32_t)__cvta_generic_to_shared(s);
    asm volatile("cp.async.cg.shared.global [%0], [%1], 16;" :: "r"(sa), "l"(g));
}
__device__ __forceinline__ void cp_commit(){ asm volatile("cp.async.commit_group;" ::: "memory"); }
template<int N> __device__ __forceinline__ void cp_wait(){
    asm volatile("cp.async.wait_group %0;" :: "n"(N) : "memory");
}
__device__ __forceinline__ uint32_t ld32bf(const __nv_bfloat16* p){
    return *reinterpret_cast<const uint32_t*>(p);
}
__device__ __forceinline__ void mma_bf16(float* c, const uint32_t* a, const uint32_t* b){
    asm volatile("mma.sync.aligned.m16n8k16.row.col.f32.bf16.bf16.f32 "
        "{%0,%1,%2,%3}, {%4,%5,%6,%7}, {%8,%9}, {%0,%1,%2,%3};"
        : "+f"(c[0]), "+f"(c[1]), "+f"(c[2]), "+f"(c[3])
        : "r"(a[0]), "r"(a[1]), "r"(a[2]), "r"(a[3]), "r"(b[0]), "r"(b[1]));
}

// ---------------------------------------------------------------------------
// Kernel T: RoPE sin/cos table (exact fp32 math matching jax reference)
// ---------------------------------------------------------------------------
__global__ void sincos_kernel(){
    int idx = blockIdx.x*blockDim.x + threadIdx.x;
    if (idx >= Sdim*32) return;
    int s = idx >> 5, j = idx & 31;
    float freq = powf(10000.0f, -(float)j * 0.03125f);
    float ang  = (float)s * freq;
    g_sin[idx] = sinf(ang);
    g_cos[idx] = cosf(ang);
}

// ---------------------------------------------------------------------------
// Prep: X (f32) -> g_Xbf (bf16), grid-stride over float2 pairs
// ---------------------------------------------------------------------------
__global__ void prep_x_kernel(const float* __restrict__ X){
    int n2 = Bdim*Sdim*Hdim/2;
    for (int i = blockIdx.x*blockDim.x + threadIdx.x; i < n2; i += gridDim.x*blockDim.x){
        float2 v = reinterpret_cast<const float2*>(X)[i];
        __nv_bfloat162 o;
        o.x = __float2bfloat16_rn(v.x);
        o.y = __float2bfloat16_rn(v.y);
        reinterpret_cast<__nv_bfloat162*>(g_Xbf)[i] = o;
    }
}

// ---------------------------------------------------------------------------
// Prep: W [k=1024][n=2048] f32 -> g_Wt [n][k] bf16 (tiled transpose)
// ---------------------------------------------------------------------------
__global__ void prep_w_kernel(const float* __restrict__ W){
    __shared__ float t[32][33];
    const int k0 = blockIdx.y*32, n0 = blockIdx.x*32;
    #pragma unroll
    for (int i = threadIdx.y; i < 32; i += 8)
        t[i][threadIdx.x] = W[(size_t)(k0+i)*NOUT + n0 + threadIdx.x];
    __syncthreads();
    #pragma unroll
    for (int i = threadIdx.y; i < 32; i += 8)
        g_Wt[(size_t)(n0+i)*Hdim + k0 + threadIdx.x] = __float2bfloat16_rn(t[threadIdx.x][i]);
}

// ---------------------------------------------------------------------------
// Kernel A: C = X@W + b, fused interleaved RoPE, scatter to g_Q/g_K (bf16).
// M=4096, N=2048, K=1024. CTA 128x64, BK=32, bf16 m16n8k16, cp.async x2.
// SMEM (bf16, stride in halves):
//   As [128][40]: 32-bit frag load word-bank = (20g+tg)... row stride 40 ->
//                 bank=(g*20+tg)%32? rows vary by g: (40/2)g+tg = 20g+tg: bijective.
//   Bs [64][40] : rows are n; n = ..+g -> bank 20g+tg: bijective.
// ---------------------------------------------------------------------------
#define A2STR 40
#define SMEM_A_BYTES ((2*128*A2STR + 2*64*A2STR)*2)

__global__ void __launch_bounds__(256) gemm1_rope_kernel(
    const float* __restrict__ bias)
{
    extern __shared__ __nv_bfloat16 smb[];
    __nv_bfloat16* As = smb;                  // [2][128][A2STR]
    __nv_bfloat16* Bs = smb + 2*128*A2STR;    // [2][64][A2STR]
    const int tid  = threadIdx.x;
    const int lane = tid & 31, warp = tid >> 5;
    const int g = lane >> 2, tg = lane & 3;
    const int wm = warp >> 1, wn = warp & 1;
    const int mtile = blockIdx.y, ntile = blockIdx.x;
    const __nv_bfloat16* Xb = g_Xbf + (size_t)mtile*128*Hdim;
    const __nv_bfloat16* Wb = g_Wt  + (size_t)ntile*64*Hdim;

    float acc[2][4][4];
    #pragma unroll
    for (int a=0;a<2;a++)
        #pragma unroll
        for (int bq=0;bq<4;bq++)
            #pragma unroll
            for (int k=0;k<4;k++) acc[a][bq][k]=0.f;

    auto load_stage = [&](int ks, int bufsel){
        __nv_bfloat16* Ad = As + bufsel*128*A2STR;
        const int k0 = ks*32;
        #pragma unroll
        for (int i=0;i<2;i++){
            int c = tid + i*256;                 // 0..511
            int row = c >> 2, ch = (c & 3) << 3; // 128 rows x 4 chunks of 8 halves
            cp16(Ad + row*A2STR + ch, Xb + (size_t)row*Hdim + k0 + ch);
        }
        __nv_bfloat16* Bd = Bs + bufsel*64*A2STR;
        {
            int row = tid >> 2, ch = (tid & 3) << 3;  // 64 rows x 4 chunks
            cp16(Bd + row*A2STR + ch, Wb + (size_t)row*Hdim + k0 + ch);
        }
        cp_commit();
    };

    load_stage(0, 0);
    int buf = 0;
    for (int ks = 0; ks < 32; ks++){
        if (ks < 31){ load_stage(ks+1, buf^1); cp_wait<1>(); }
        else        { cp_wait<0>(); }
        __syncthreads();
        const __nv_bfloat16* Ab = As + buf*128*A2STR;
        const __nv_bfloat16* Bb = Bs + buf*64*A2STR;
        #pragma unroll
        for (int kk=0; kk<2; kk++){
            const int k0 = kk*16;
            uint32_t af[2][4], bf[4][2];
            #pragma unroll
            for (int mt=0; mt<2; mt++){
                int rb = wm*32 + mt*16;
                af[mt][0] = ld32bf(Ab + (rb+g  )*A2STR + k0 + 2*tg    );
                af[mt][1] = ld32bf(Ab + (rb+g+8)*A2STR + k0 + 2*tg    );
                af[mt][2] = ld32bf(Ab + (rb+g  )*A2STR + k0 + 2*tg + 8);
                af[mt][3] = ld32bf(Ab + (rb+g+8)*A2STR + k0 + 2*tg + 8);
            }
            #pragma unroll
            for (int nt=0; nt<4; nt++){
                int nb = wn*32 + nt*8 + g;
                bf[nt][0] = ld32bf(Bb + nb*A2STR + k0 + 2*tg    );
                bf[nt][1] = ld32bf(Bb + nb*A2STR + k0 + 2*tg + 8);
            }
            #pragma unroll
            for (int mt=0; mt<2; mt++)
                #pragma unroll
                for (int nt=0; nt<4; nt++)
                    mma_bf16(acc[mt][nt], af[mt], bf[nt]);
        }
        __syncthreads();
        buf ^= 1;
    }

    // Epilogue: bias + RoPE (interleaved pair == c0/c1 accumulator pair), bf16 out
    #pragma unroll
    for (int nt=0; nt<4; nt++){
        const int n_loc = wn*32 + nt*8 + 2*tg;
        const int c = ntile*64 + n_loc;          // even
        const int h = c >> 7, r = c & 127;
        const int d = r & 63, jj = d >> 1;
        __nv_bfloat16* dst = (r < 64) ? g_Q : g_K;
        const float b0 = bias[c], b1 = bias[c+1];
        #pragma unroll
        for (int mt=0; mt<2; mt++){
            #pragma unroll
            for (int p=0; p<2; p++){
                int m = mtile*128 + wm*32 + mt*16 + g + p*8;
                int bb = m >> 10, s = m & 1023;
                float sv = g_sin[s*32 + jj], cv = g_cos[s*32 + jj];
                float v0 = acc[mt][nt][2*p]   + b0;
                float v1 = acc[mt][nt][2*p+1] + b1;
                __nv_bfloat162 o;
                o.x = __float2bfloat16_rn(v0*cv - v1*sv);
                o.y = __float2bfloat16_rn(v1*cv + v0*sv);
                int idx = ((bb*ENTn + h)*Sdim + s)*INNER + d;
                *reinterpret_cast<__nv_bfloat162*>(dst + idx) = o;
            }
        }
    }
}

// ---------------------------------------------------------------------------
// Kernel B: logits[z=(b,h)][m][n] = (Q[m]·K[n]) masked/scaled. 128x128 tiles.
// Strictly-lower tiles: exact constant, float4 streaming stores.
// Upper/diagonal: bf16 m16n8k16 over d=64. Q/K in bf16 -> single LDS.32 frags.
//   Qs/Ks [128][72] halves: frag bank = (36g+tg)%32 = 4g+tg: bijective.
// ---------------------------------------------------------------------------
#define QK2STR 72
#define SMEM_B_BYTES (2*128*QK2STR*2)

__global__ void __launch_bounds__(256) attn_logits_kernel(
    const float* __restrict__ tok, float* __restrict__ out)
{
    const int ntile = blockIdx.x, mtile = blockIdx.y, z = blockIdx.z;
    const int bidx = z >> 4;
    const int tid = threadIdx.x;
    float* outb = out + ((size_t)z << 20);
    const float* padp = tok + bidx*Sdim + ntile*128;

    if (ntile < mtile){
        // fully-masked tile: value = (-(1-pad)*NEG - NEG)/8, exact vs reference
        const int n4 = (tid & 31) << 2;
        const int m0 = mtile*128 + (tid >> 5);
        float4 pv = *reinterpret_cast<const float4*>(padp + n4);
        float4 val;
        val.x = (-(1.0f - pv.x)*NEGC - NEGC)*0.125f;
        val.y = (-(1.0f - pv.y)*NEGC - NEGC)*0.125f;
        val.z = (-(1.0f - pv.z)*NEGC - NEGC)*0.125f;
        val.w = (-(1.0f - pv.w)*NEGC - NEGC)*0.125f;
        const int ncol = ntile*128 + n4;
        #pragma unroll
        for (int i=0;i<16;i++)
            *reinterpret_cast<float4*>(outb + ((size_t)(m0 + i*8) << 10) + ncol) = val;
        return;
    }

    extern __shared__ __nv_bfloat16 smb[];
    __nv_bfloat16* Qs = smb;                 // [128][QK2STR]
    __nv_bfloat16* Ks = smb + 128*QK2STR;
    __shared__ float pad_s[128];
    if (tid < 128) pad_s[tid] = padp[tid];

    const __nv_bfloat16* Qg = g_Q + ((size_t)z*Sdim + (size_t)mtile*128)*INNER;
    const __nv_bfloat16* Kg = g_K + ((size_t)z*Sdim + (size_t)ntile*128)*INNER;
    #pragma unroll
    for (int i=0;i<4;i++){
        int t = tid + i*256;                  // 0..1023
        int row = t >> 3, ch = (t & 7) << 3;  // 128 rows x 8 chunks of 8 halves
        cp16(Qs + row*QK2STR + ch, Qg + row*INNER + ch);
        cp16(Ks + row*QK2STR + ch, Kg + row*INNER + ch);
    }
    cp_commit();
    cp_wait<0>();
    __syncthreads();

    const int lane = tid & 31, warp = tid >> 5;
    const int g = lane >> 2, tg = lane & 3;
    const int wm = warp >> 1, wn = warp & 1;   // 4 x 2 warps, warp tile 32x64

    float acc[2][8][4];
    #pragma unroll
    for (int a=0;a<2;a++)
        #pragma unroll
        for (int bq=0;bq<8;bq++)
            #pragma unroll
            for (int k=0;k<4;k++) acc[a][bq][k]=0.f;

    #pragma unroll
    for (int kk=0; kk<4; kk++){
        const int k0 = kk*16;
        uint32_t af[2][4], bf[8][2];
        #pragma unroll
        for (int mt=0; mt<2; mt++){
            int rb = wm*32 + mt*16;
            af[mt][0] = ld32bf(Qs + (rb+g  )*QK2STR + k0 + 2*tg    );
            af[mt][1] = ld32bf(Qs + (rb+g+8)*QK2STR + k0 + 2*tg    );
            af[mt][2] = ld32bf(Qs + (rb+g  )*QK2STR + k0 + 2*tg + 8);
            af[mt][3] = ld32bf(Qs + (rb+g+8)*QK2STR + k0 + 2*tg + 8);
        }
        #pragma unroll
        for (int nt=0; nt<8; nt++){
            int nb = wn*64 + nt*8 + g;
            bf[nt][0] = ld32bf(Ks + nb*QK2STR + k0 + 2*tg    );
            bf[nt][1] = ld32bf(Ks + nb*QK2STR + k0 + 2*tg + 8);
        }
        #pragma unroll
        for (int mt=0; mt<2; mt++)
            #pragma unroll
            for (int nt=0; nt<8; nt++)
                mma_bf16(acc[mt][nt], af[mt], bf[nt]);
    }

    #pragma unroll
    for (int mt=0; mt<2; mt++){
        #pragma unroll
        for (int nt=0; nt<8; nt++){
            const int n_loc = wn*64 + nt*8 + 2*tg;
            const int n = ntile*128 + n_loc;
            const float p0 = pad_s[n_loc], p1 = pad_s[n_loc+1];
            #pragma unroll
            for (int p=0; p<2; p++){
                const int m = mtile*128 + wm*32 + mt*16 + g + p*8;
                float v0 = acc[mt][nt][2*p]   * p0 - (1.0f - p0)*NEGC - ((n   < m) ? NEGC : 0.0f);
                float v1 = acc[mt][nt][2*p+1] * p1 - (1.0f - p1)*NEGC - ((n+1 < m) ? NEGC : 0.0f);
                *reinterpret_cast<float2*>(outb + ((size_t)m << 10) + n) =
                    make_float2(v0*0.125f, v1*0.125f);
            }
        }
    }
}

// ---------------------------------------------------------------------------
extern "C" void kernel_launch(void* const* d_in, const int* in_sizes, int n_in,
                              void* d_out, int out_size)
{
    const float* X    = (const float*)d_in[0];
    const float* W    = (const float*)d_in[1];
    const float* bias = (const float*)d_in[2];
    const float* tok  = (const float*)d_in[3];
    float* out = (float*)d_out;

    cudaFuncSetAttribute(gemm1_rope_kernel,
        cudaFuncAttributeMaxDynamicSharedMemorySize, SMEM_A_BYTES);
    cudaFuncSetAttribute(attn_logits_kernel,
        cudaFuncAttributeMaxDynamicSharedMemorySize, SMEM_B_BYTES);

    sincos_kernel<<<64, 512>>>();
    prep_x_kernel<<<512, 256>>>(X);
    prep_w_kernel<<<dim3(64, 32), dim3(32, 8)>>>(W);
    gemm1_rope_kernel<<<dim3(32, 32), 256, SMEM_A_BYTES>>>(bias);
    attn_logits_kernel<<<dim3(8, 8, 64), 256, SMEM_B_BYTES>>>(tok, out);
}

// round 7
// speedup vs baseline: 1.4304x; 1.0999x over previous
#include <cuda_runtime.h>
#include <cuda_bf16.h>
#include <cstdint>

#define Bdim  4
#define Sdim  1024
#define Hdim  1024
#define ENTn  16
#define INNER 64
#define NOUT  2048
#define NEGC  1.0e12f

// Scratch (allocation-free rule: __device__ globals)
__device__ __nv_bfloat16 g_Q[Bdim*ENTn*Sdim*INNER];   // [b][h][s][d] bf16
__device__ __nv_bfloat16 g_K[Bdim*ENTn*Sdim*INNER];
__device__ __nv_bfloat16 g_Xbf[Bdim*Sdim*Hdim];       // X in bf16 [m][k]
__device__ __nv_bfloat16 g_Wt[NOUT*Hdim];             // W^T in bf16 [n][k]
__device__ float g_sin[Sdim*(INNER/2)];               // [s][j]
__device__ float g_cos[Sdim*(INNER/2)];

__device__ __forceinline__ void cp16(void* s, const void* g){
    uint32_t sa = (uint32_t)__cvta_generic_to_shared(s);
    asm volatile("cp.async.cg.shared.global [%0], [%1], 16;" :: "r"(sa), "l"(g));
}
__device__ __forceinline__ void cp_commit(){ asm volatile("cp.async.commit_group;" ::: "memory"); }
template<int N> __device__ __forceinline__ void cp_wait(){
    asm volatile("cp.async.wait_group %0;" :: "n"(N) : "memory");
}
__device__ __forceinline__ void ldsm_x4(uint32_t* r, uint32_t addr){
    asm volatile("ldmatrix.sync.aligned.m8n8.x4.shared.b16 {%0,%1,%2,%3}, [%4];"
        : "=r"(r[0]), "=r"(r[1]), "=r"(r[2]), "=r"(r[3]) : "r"(addr));
}
__device__ __forceinline__ void mma_bf16(float* c, const uint32_t* a, const uint32_t* b){
    asm volatile("mma.sync.aligned.m16n8k16.row.col.f32.bf16.bf16.f32 "
        "{%0,%1,%2,%3}, {%4,%5,%6,%7}, {%8,%9}, {%0,%1,%2,%3};"
        : "+f"(c[0]), "+f"(c[1]), "+f"(c[2]), "+f"(c[3])
        : "r"(a[0]), "r"(a[1]), "r"(a[2]), "r"(a[3]), "r"(b[0]), "r"(b[1]));
}

// ---------------------------------------------------------------------------
// Kernel T: RoPE sin/cos table (exact fp32 math matching jax reference)
// ---------------------------------------------------------------------------
__global__ void sincos_kernel(){
    int idx = blockIdx.x*blockDim.x + threadIdx.x;
    if (idx >= Sdim*32) return;
    int s = idx >> 5, j = idx & 31;
    float freq = powf(10000.0f, -(float)j * 0.03125f);
    float ang  = (float)s * freq;
    g_sin[idx] = sinf(ang);
    g_cos[idx] = cosf(ang);
}

// ---------------------------------------------------------------------------
// Prep: X (f32) -> g_Xbf (bf16)
// ---------------------------------------------------------------------------
__global__ void prep_x_kernel(const float* __restrict__ X){
    int n2 = Bdim*Sdim*Hdim/2;
    for (int i = blockIdx.x*blockDim.x + threadIdx.x; i < n2; i += gridDim.x*blockDim.x){
        float2 v = reinterpret_cast<const float2*>(X)[i];
        __nv_bfloat162 o;
        o.x = __float2bfloat16_rn(v.x);
        o.y = __float2bfloat16_rn(v.y);
        reinterpret_cast<__nv_bfloat162*>(g_Xbf)[i] = o;
    }
}

// ---------------------------------------------------------------------------
// Prep: W [k][n] f32 -> g_Wt [n][k] bf16 (tiled transpose)
// ---------------------------------------------------------------------------
__global__ void prep_w_kernel(const float* __restrict__ W){
    __shared__ float t[32][33];
    const int k0 = blockIdx.y*32, n0 = blockIdx.x*32;
    #pragma unroll
    for (int i = threadIdx.y; i < 32; i += 8)
        t[i][threadIdx.x] = W[(size_t)(k0+i)*NOUT + n0 + threadIdx.x];
    __syncthreads();
    #pragma unroll
    for (int i = threadIdx.y; i < 32; i += 8)
        g_Wt[(size_t)(n0+i)*Hdim + k0 + threadIdx.x] = __float2bfloat16_rn(t[threadIdx.x][i]);
}

// ---------------------------------------------------------------------------
// Kernel A: C = X@W + b, fused interleaved RoPE, scatter to g_Q/g_K (bf16).
// M=4096, N=2048, K=1024. CTA tile 128x128, BK=64 halves, double-buffered
// cp.async, ldmatrix.x4 fragment loads (stride 72 halves = 144B: LDSM phases
// conflict-free, 16B aligned). 8 warps: wm=warp>>1 (32 m-rows), wn=warp&1
// (64 n-cols); warp tile 32x64, 16 HMMA per k16-step.
// ---------------------------------------------------------------------------
#define G1STR 72
#define SMEM_A_BYTES (4*128*G1STR*2)   // A[2] + B[2] buffers, 73728 B

__global__ void __launch_bounds__(256) gemm1_rope_kernel(
    const float* __restrict__ bias)
{
    extern __shared__ __nv_bfloat16 smb[];
    const uint32_t sbase = (uint32_t)__cvta_generic_to_shared(smb);
    const int tid  = threadIdx.x;
    const int lane = tid & 31, warp = tid >> 5;
    const int g = lane >> 2, tg = lane & 3;
    const int wm = warp >> 1, wn = warp & 1;
    const int mtile = blockIdx.y, ntile = blockIdx.x;   // grid (16, 32)
    const __nv_bfloat16* Xb = g_Xbf + (size_t)mtile*128*Hdim;
    const __nv_bfloat16* Wb = g_Wt  + (size_t)ntile*128*Hdim;

    // per-lane ldmatrix row/chunk decomposition
    const int l7   = lane & 7;
    const int selA_r = ((lane >> 3) & 1) * 8;   // A: row += , chunk += (lane>>4)*8
    const int selA_c = (lane >> 4) * 8;
    const int selB_r = (lane >> 4) * 8;         // B: row += , chunk += ((lane>>3)&1)*8
    const int selB_c = ((lane >> 3) & 1) * 8;

    float acc[2][8][4];
    #pragma unroll
    for (int a=0;a<2;a++)
        #pragma unroll
        for (int bq=0;bq<8;bq++)
            #pragma unroll
            for (int k=0;k<4;k++) acc[a][bq][k]=0.f;

    auto load_stage = [&](int ks, int b){
        __nv_bfloat16* Ad = smb + b*128*G1STR;
        __nv_bfloat16* Bd = smb + (2+b)*128*G1STR;
        const __nv_bfloat16* xs = Xb + ks*64;
        const __nv_bfloat16* ws = Wb + ks*64;
        #pragma unroll
        for (int i=0;i<4;i++){
            int c = tid + i*256;                 // 0..1023
            int row = c >> 3, ch = (c & 7) << 3; // 128 rows x 8 chunks of 8 halves
            cp16(Ad + row*G1STR + ch, xs + (size_t)row*Hdim + ch);
            cp16(Bd + row*G1STR + ch, ws + (size_t)row*Hdim + ch);
        }
        cp_commit();
    };

    load_stage(0, 0);
    int buf = 0;
    for (int ks = 0; ks < 16; ks++){
        if (ks < 15){ load_stage(ks+1, buf^1); cp_wait<1>(); }
        else        { cp_wait<0>(); }
        __syncthreads();
        const uint32_t abase = sbase + (buf*128*G1STR)*2;
        const uint32_t bbase = sbase + ((2+buf)*128*G1STR)*2;
        #pragma unroll
        for (int kk=0; kk<4; kk++){
            const int k0 = kk*16;
            uint32_t af[2][4], bf[8][2];
            #pragma unroll
            for (int mt=0; mt<2; mt++){
                int row = wm*32 + mt*16 + selA_r + l7;
                ldsm_x4(af[mt], abase + (row*G1STR + k0 + selA_c)*2);
            }
            #pragma unroll
            for (int ntp=0; ntp<4; ntp++){
                int row = wn*64 + ntp*16 + selB_r + l7;
                uint32_t q[4];
                ldsm_x4(q, bbase + (row*G1STR + k0 + selB_c)*2);
                bf[2*ntp  ][0] = q[0]; bf[2*ntp  ][1] = q[1];
                bf[2*ntp+1][0] = q[2]; bf[2*ntp+1][1] = q[3];
            }
            #pragma unroll
            for (int mt=0; mt<2; mt++)
                #pragma unroll
                for (int nt=0; nt<8; nt++)
                    mma_bf16(acc[mt][nt], af[mt], bf[nt]);
        }
        __syncthreads();
        buf ^= 1;
    }

    // Epilogue: bias + RoPE (interleaved pair == c0/c1 accumulator pair), bf16 out
    #pragma unroll
    for (int nt=0; nt<8; nt++){
        const int n_loc = wn*64 + nt*8 + 2*tg;
        const int c = ntile*128 + n_loc;         // even
        const int h = c >> 7, r = c & 127;
        const int d = r & 63, jj = d >> 1;
        __nv_bfloat16* dst = (r < 64) ? g_Q : g_K;
        const float b0 = bias[c], b1 = bias[c+1];
        #pragma unroll
        for (int mt=0; mt<2; mt++){
            #pragma unroll
            for (int p=0; p<2; p++){
                int m = mtile*128 + wm*32 + mt*16 + g + p*8;
                int bb = m >> 10, s = m & 1023;
                float sv = g_sin[s*32 + jj], cv = g_cos[s*32 + jj];
                float v0 = acc[mt][nt][2*p]   + b0;
                float v1 = acc[mt][nt][2*p+1] + b1;
                __nv_bfloat162 o;
                o.x = __float2bfloat16_rn(v0*cv - v1*sv);
                o.y = __float2bfloat16_rn(v1*cv + v0*sv);
                int idx = ((bb*ENTn + h)*Sdim + s)*INNER + d;
                *reinterpret_cast<__nv_bfloat162*>(dst + idx) = o;
            }
        }
    }
}

// ---------------------------------------------------------------------------
// Kernel B: logits[z=(b,h)][m][n] = (Q[m]·K[n]) masked/scaled. 128x128 tiles.
// Strictly-lower tiles: exact constant, float4 streaming stores.
// Upper/diagonal: bf16 m16n8k16 over d=64, ldmatrix fragment loads.
// ---------------------------------------------------------------------------
#define QK2STR 72
#define SMEM_B_BYTES (2*128*QK2STR*2)

__global__ void __launch_bounds__(256) attn_logits_kernel(
    const float* __restrict__ tok, float* __restrict__ out)
{
    const int ntile = blockIdx.x, mtile = blockIdx.y, z = blockIdx.z;
    const int bidx = z >> 4;
    const int tid = threadIdx.x;
    float* outb = out + ((size_t)z << 20);
    const float* padp = tok + bidx*Sdim + ntile*128;

    if (ntile < mtile){
        const int n4 = (tid & 31) << 2;
        const int m0 = mtile*128 + (tid >> 5);
        float4 pv = *reinterpret_cast<const float4*>(padp + n4);
        float4 val;
        val.x = (-(1.0f - pv.x)*NEGC - NEGC)*0.125f;
        val.y = (-(1.0f - pv.y)*NEGC - NEGC)*0.125f;
        val.z = (-(1.0f - pv.z)*NEGC - NEGC)*0.125f;
        val.w = (-(1.0f - pv.w)*NEGC - NEGC)*0.125f;
        const int ncol = ntile*128 + n4;
        #pragma unroll
        for (int i=0;i<16;i++)
            *reinterpret_cast<float4*>(outb + ((size_t)(m0 + i*8) << 10) + ncol) = val;
        return;
    }

    extern __shared__ __nv_bfloat16 smb[];
    const uint32_t sbase = (uint32_t)__cvta_generic_to_shared(smb);
    __nv_bfloat16* Qs = smb;                 // [128][QK2STR]
    __nv_bfloat16* Ks = smb + 128*QK2STR;
    __shared__ float pad_s[128];
    if (tid < 128) pad_s[tid] = padp[tid];

    const __nv_bfloat16* Qg = g_Q + ((size_t)z*Sdim + (size_t)mtile*128)*INNER;
    const __nv_bfloat16* Kg = g_K + ((size_t)z*Sdim + (size_t)ntile*128)*INNER;
    #pragma unroll
    for (int i=0;i<4;i++){
        int t = tid + i*256;
        int row = t >> 3, ch = (t & 7) << 3;
        cp16(Qs + row*QK2STR + ch, Qg + row*INNER + ch);
        cp16(Ks + row*QK2STR + ch, Kg + row*INNER + ch);
    }
    cp_commit();
    cp_wait<0>();
    __syncthreads();

    const int lane = tid & 31, warp = tid >> 5;
    const int g = lane >> 2, tg = lane & 3;
    const int wm = warp >> 1, wn = warp & 1;
    const int l7   = lane & 7;
    const int selA_r = ((lane >> 3) & 1) * 8;
    const int selA_c = (lane >> 4) * 8;
    const int selB_r = (lane >> 4) * 8;
    const int selB_c = ((lane >> 3) & 1) * 8;
    const uint32_t qbase = sbase;
    const uint32_t kbase = sbase + (128*QK2STR)*2;

    float acc[2][8][4];
    #pragma unroll
    for (int a=0;a<2;a++)
        #pragma unroll
        for (int bq=0;bq<8;bq++)
            #pragma unroll
            for (int k=0;k<4;k++) acc[a][bq][k]=0.f;

    #pragma unroll
    for (int kk=0; kk<4; kk++){
        const int k0 = kk*16;
        uint32_t af[2][4], bf[8][2];
        #pragma unroll
        for (int mt=0; mt<2; mt++){
            int row = wm*32 + mt*16 + selA_r + l7;
            ldsm_x4(af[mt], qbase + (row*QK2STR + k0 + selA_c)*2);
        }
        #pragma unroll
        for (int ntp=0; ntp<4; ntp++){
            int row = wn*64 + ntp*16 + selB_r + l7;
            uint32_t q[4];
            ldsm_x4(q, kbase + (row*QK2STR + k0 + selB_c)*2);
            bf[2*ntp  ][0] = q[0]; bf[2*ntp  ][1] = q[1];
            bf[2*ntp+1][0] = q[2]; bf[2*ntp+1][1] = q[3];
        }
        #pragma unroll
        for (int mt=0; mt<2; mt++)
            #pragma unroll
            for (int nt=0; nt<8; nt++)
                mma_bf16(acc[mt][nt], af[mt], bf[nt]);
    }

    #pragma unroll
    for (int mt=0; mt<2; mt++){
        #pragma unroll
        for (int nt=0; nt<8; nt++){
            const int n_loc = wn*64 + nt*8 + 2*tg;
            const int n = ntile*128 + n_loc;
            const float p0 = pad_s[n_loc], p1 = pad_s[n_loc+1];
            #pragma unroll
            for (int p=0; p<2; p++){
                const int m = mtile*128 + wm*32 + mt*16 + g + p*8;
                float v0 = acc[mt][nt][2*p]   * p0 - (1.0f - p0)*NEGC - ((n   < m) ? NEGC : 0.0f);
                float v1 = acc[mt][nt][2*p+1] * p1 - (1.0f - p1)*NEGC - ((n+1 < m) ? NEGC : 0.0f);
                *reinterpret_cast<float2*>(outb + ((size_t)m << 10) + n) =
                    make_float2(v0*0.125f, v1*0.125f);
            }
        }
    }
}

// ---------------------------------------------------------------------------
extern "C" void kernel_launch(void* const* d_in, const int* in_sizes, int n_in,
                              void* d_out, int out_size)
{
    const float* X    = (const float*)d_in[0];
    const float* W    = (const float*)d_in[1];
    const float* bias = (const float*)d_in[2];
    const float* tok  = (const float*)d_in[3];
    float* out = (float*)d_out;

    cudaFuncSetAttribute(gemm1_rope_kernel,
        cudaFuncAttributeMaxDynamicSharedMemorySize, SMEM_A_BYTES);
    cudaFuncSetAttribute(attn_logits_kernel,
        cudaFuncAttributeMaxDynamicSharedMemorySize, SMEM_B_BYTES);

    sincos_kernel<<<64, 512>>>();
    prep_x_kernel<<<512, 256>>>(X);
    prep_w_kernel<<<dim3(64, 32), dim3(32, 8)>>>(W);
    gemm1_rope_kernel<<<dim3(16, 32), 256, SMEM_A_BYTES>>>(bias);
    attn_logits_kernel<<<dim3(8, 8, 64), 256, SMEM_B_BYTES>>>(tok, out);
}

// round 8
// speedup vs baseline: 1.4437x; 1.0093x over previous
#include <cuda_runtime.h>
#include <cuda_bf16.h>
#include <cstdint>

#define Bdim  4
#define Sdim  1024
#define Hdim  1024
#define ENTn  16
#define INNER 64
#define NOUT  2048
#define NEGC  1.0e12f

// Scratch (allocation-free rule: __device__ globals)
__device__ __nv_bfloat16 g_Q[Bdim*ENTn*Sdim*INNER];   // [b][h][s][d] bf16
__device__ __nv_bfloat16 g_K[Bdim*ENTn*Sdim*INNER];
__device__ __nv_bfloat16 g_Xbf[Bdim*Sdim*Hdim];       // X in bf16 [m][k]
__device__ __nv_bfloat16 g_Wt[NOUT*Hdim];             // W^T in bf16 [n][k]
__device__ float g_sin[Sdim*(INNER/2)];               // [s][j]
__device__ float g_cos[Sdim*(INNER/2)];

__device__ __forceinline__ void cp16(void* s, const void* g){
    uint32_t sa = (uint32_t)__cvta_generic_to_shared(s);
    asm volatile("cp.async.cg.shared.global [%0], [%1], 16;" :: "r"(sa), "l"(g));
}
__device__ __forceinline__ void cp_commit(){ asm volatile("cp.async.commit_group;" ::: "memory"); }
template<int N> __device__ __forceinline__ void cp_wait(){
    asm volatile("cp.async.wait_group %0;" :: "n"(N) : "memory");
}
__device__ __forceinline__ void ldsm_x4(uint32_t* r, uint32_t addr){
    asm volatile("ldmatrix.sync.aligned.m8n8.x4.shared.b16 {%0,%1,%2,%3}, [%4];"
        : "=r"(r[0]), "=r"(r[1]), "=r"(r[2]), "=r"(r[3]) : "r"(addr));
}
__device__ __forceinline__ void mma_bf16(float* c, const uint32_t* a, const uint32_t* b){
    asm volatile("mma.sync.aligned.m16n8k16.row.col.f32.bf16.bf16.f32 "
        "{%0,%1,%2,%3}, {%4,%5,%6,%7}, {%8,%9}, {%0,%1,%2,%3};"
        : "+f"(c[0]), "+f"(c[1]), "+f"(c[2]), "+f"(c[3])
        : "r"(a[0]), "r"(a[1]), "r"(a[2]), "r"(a[3]), "r"(b[0]), "r"(b[1]));
}
__device__ __forceinline__ void stg_cs_f2(float* p, float x, float y){
    asm volatile("st.global.cs.v2.f32 [%0], {%1,%2};" :: "l"(p), "f"(x), "f"(y) : "memory");
}
__device__ __forceinline__ void stg_cs_f4(float* p, float4 v){
    asm volatile("st.global.cs.v4.f32 [%0], {%1,%2,%3,%4};"
        :: "l"(p), "f"(v.x), "f"(v.y), "f"(v.z), "f"(v.w) : "memory");
}

// ---------------------------------------------------------------------------
// Kernel T: RoPE sin/cos table (exact fp32 math matching jax reference)
// ---------------------------------------------------------------------------
__global__ void sincos_kernel(){
    int idx = blockIdx.x*blockDim.x + threadIdx.x;
    if (idx >= Sdim*32) return;
    int s = idx >> 5, j = idx & 31;
    float freq = powf(10000.0f, -(float)j * 0.03125f);
    float ang  = (float)s * freq;
    g_sin[idx] = sinf(ang);
    g_cos[idx] = cosf(ang);
}

// ---------------------------------------------------------------------------
// Prep: X (f32) -> g_Xbf (bf16)
// ---------------------------------------------------------------------------
__global__ void prep_x_kernel(const float* __restrict__ X){
    int n2 = Bdim*Sdim*Hdim/2;
    for (int i = blockIdx.x*blockDim.x + threadIdx.x; i < n2; i += gridDim.x*blockDim.x){
        float2 v = reinterpret_cast<const float2*>(X)[i];
        __nv_bfloat162 o;
        o.x = __float2bfloat16_rn(v.x);
        o.y = __float2bfloat16_rn(v.y);
        reinterpret_cast<__nv_bfloat162*>(g_Xbf)[i] = o;
    }
}

// ---------------------------------------------------------------------------
// Prep: W [k][n] f32 -> g_Wt [n][k] bf16 (tiled transpose)
// ---------------------------------------------------------------------------
__global__ void prep_w_kernel(const float* __restrict__ W){
    __shared__ float t[32][33];
    const int k0 = blockIdx.y*32, n0 = blockIdx.x*32;
    #pragma unroll
    for (int i = threadIdx.y; i < 32; i += 8)
        t[i][threadIdx.x] = W[(size_t)(k0+i)*NOUT + n0 + threadIdx.x];
    __syncthreads();
    #pragma unroll
    for (int i = threadIdx.y; i < 32; i += 8)
        g_Wt[(size_t)(n0+i)*Hdim + k0 + threadIdx.x] = __float2bfloat16_rn(t[threadIdx.x][i]);
}

// ---------------------------------------------------------------------------
// Kernel A: C = X@W + b, fused interleaved RoPE, scatter to g_Q/g_K (bf16).
// M=4096, N=2048, K=1024. CTA tile 128x128, 4 warps, warp tile 64x64:
// per k16-step 8 LDSM.x4 -> 32 HMMA (ratio 4). BK=64 halves, double-buffered
// cp.async, stride 72 halves (144B): LDSM rows 36 banks apart -> 4r mod 32,
// conflict-free; 16B aligned.
// ---------------------------------------------------------------------------
#define G1STR 72
#define SMEM_A_BYTES (4*128*G1STR*2)   // A[2] + B[2] buffers, 73728 B

__global__ void __launch_bounds__(128, 2) gemm1_rope_kernel(
    const float* __restrict__ bias)
{
    extern __shared__ __nv_bfloat16 smb[];
    const uint32_t sbase = (uint32_t)__cvta_generic_to_shared(smb);
    const int tid  = threadIdx.x;
    const int lane = tid & 31, warp = tid >> 5;
    const int g = lane >> 2, tg = lane & 3;
    const int wm = warp >> 1, wn = warp & 1;          // 2x2 warps, 64x64 tiles
    const int mtile = blockIdx.y, ntile = blockIdx.x; // grid (16, 32)
    const __nv_bfloat16* Xb = g_Xbf + (size_t)mtile*128*Hdim;
    const __nv_bfloat16* Wb = g_Wt  + (size_t)ntile*128*Hdim;

    const int l7   = lane & 7;
    const int selA_r = ((lane >> 3) & 1) * 8;
    const int selA_c = (lane >> 4) * 8;
    const int selB_r = (lane >> 4) * 8;
    const int selB_c = ((lane >> 3) & 1) * 8;

    float acc[4][8][4];
    #pragma unroll
    for (int a=0;a<4;a++)
        #pragma unroll
        for (int bq=0;bq<8;bq++)
            #pragma unroll
            for (int k=0;k<4;k++) acc[a][bq][k]=0.f;

    auto load_stage = [&](int ks, int b){
        __nv_bfloat16* Ad = smb + b*128*G1STR;
        __nv_bfloat16* Bd = smb + (2+b)*128*G1STR;
        const __nv_bfloat16* xs = Xb + ks*64;
        const __nv_bfloat16* ws = Wb + ks*64;
        #pragma unroll
        for (int i=0;i<8;i++){
            int c = tid + i*128;                 // 0..1023
            int row = c >> 3, ch = (c & 7) << 3; // 128 rows x 8 chunks of 8 halves
            cp16(Ad + row*G1STR + ch, xs + (size_t)row*Hdim + ch);
            cp16(Bd + row*G1STR + ch, ws + (size_t)row*Hdim + ch);
        }
        cp_commit();
    };

    load_stage(0, 0);
    int buf = 0;
    for (int ks = 0; ks < 16; ks++){
        if (ks < 15){ load_stage(ks+1, buf^1); cp_wait<1>(); }
        else        { cp_wait<0>(); }
        __syncthreads();
        const uint32_t abase = sbase + (buf*128*G1STR)*2;
        const uint32_t bbase = sbase + ((2+buf)*128*G1STR)*2;
        #pragma unroll
        for (int kk=0; kk<4; kk++){
            const int k0 = kk*16;
            uint32_t af[4][4], bf[8][2];
            #pragma unroll
            for (int mt=0; mt<4; mt++){
                int row = wm*64 + mt*16 + selA_r + l7;
                ldsm_x4(af[mt], abase + (row*G1STR + k0 + selA_c)*2);
            }
            #pragma unroll
            for (int ntp=0; ntp<4; ntp++){
                int row = wn*64 + ntp*16 + selB_r + l7;
                uint32_t q[4];
                ldsm_x4(q, bbase + (row*G1STR + k0 + selB_c)*2);
                bf[2*ntp  ][0] = q[0]; bf[2*ntp  ][1] = q[1];
                bf[2*ntp+1][0] = q[2]; bf[2*ntp+1][1] = q[3];
            }
            #pragma unroll
            for (int mt=0; mt<4; mt++)
                #pragma unroll
                for (int nt=0; nt<8; nt++)
                    mma_bf16(acc[mt][nt], af[mt], bf[nt]);
        }
        __syncthreads();
        buf ^= 1;
    }

    // Epilogue: bias + RoPE (interleaved pair == c0/c1 accumulator pair), bf16 out
    #pragma unroll
    for (int nt=0; nt<8; nt++){
        const int n_loc = wn*64 + nt*8 + 2*tg;
        const int c = ntile*128 + n_loc;         // even
        const int h = c >> 7, r = c & 127;
        const int d = r & 63, jj = d >> 1;
        __nv_bfloat16* dst = (r < 64) ? g_Q : g_K;
        const float b0 = bias[c], b1 = bias[c+1];
        #pragma unroll
        for (int mt=0; mt<4; mt++){
            #pragma unroll
            for (int p=0; p<2; p++){
                int m = mtile*128 + wm*64 + mt*16 + g + p*8;
                int bb = m >> 10, s = m & 1023;
                float sv = g_sin[s*32 + jj], cv = g_cos[s*32 + jj];
                float v0 = acc[mt][nt][2*p]   + b0;
                float v1 = acc[mt][nt][2*p+1] + b1;
                __nv_bfloat162 o;
                o.x = __float2bfloat16_rn(v0*cv - v1*sv);
                o.y = __float2bfloat16_rn(v1*cv + v0*sv);
                int idx = ((bb*ENTn + h)*Sdim + s)*INNER + d;
                *reinterpret_cast<__nv_bfloat162*>(dst + idx) = o;
            }
        }
    }
}

// ---------------------------------------------------------------------------
// Kernel B: logits[z=(b,h)][m][n] = (Q[m]·K[n]) masked/scaled. 128x128 tiles.
// Strictly-lower tiles: exact constant, streaming float4 stores.
// Upper/diagonal: bf16 m16n8k16 over d=64, ldmatrix fragment loads,
// streaming (st.global.cs) output stores.
// ---------------------------------------------------------------------------
#define QK2STR 72
#define SMEM_B_BYTES (2*128*QK2STR*2)

__global__ void __launch_bounds__(256) attn_logits_kernel(
    const float* __restrict__ tok, float* __restrict__ out)
{
    const int ntile = blockIdx.x, mtile = blockIdx.y, z = blockIdx.z;
    const int bidx = z >> 4;
    const int tid = threadIdx.x;
    float* outb = out + ((size_t)z << 20);
    const float* padp = tok + bidx*Sdim + ntile*128;

    if (ntile < mtile){
        const int n4 = (tid & 31) << 2;
        const int m0 = mtile*128 + (tid >> 5);
        float4 pv = *reinterpret_cast<const float4*>(padp + n4);
        float4 val;
        val.x = (-(1.0f - pv.x)*NEGC - NEGC)*0.125f;
        val.y = (-(1.0f - pv.y)*NEGC - NEGC)*0.125f;
        val.z = (-(1.0f - pv.z)*NEGC - NEGC)*0.125f;
        val.w = (-(1.0f - pv.w)*NEGC - NEGC)*0.125f;
        const int ncol = ntile*128 + n4;
        #pragma unroll
        for (int i=0;i<16;i++)
            stg_cs_f4(outb + ((size_t)(m0 + i*8) << 10) + ncol, val);
        return;
    }

    extern __shared__ __nv_bfloat16 smb[];
    const uint32_t sbase = (uint32_t)__cvta_generic_to_shared(smb);
    __nv_bfloat16* Qs = smb;                 // [128][QK2STR]
    __nv_bfloat16* Ks = smb + 128*QK2STR;
    __shared__ float pad_s[128];
    if (tid < 128) pad_s[tid] = padp[tid];

    const __nv_bfloat16* Qg = g_Q + ((size_t)z*Sdim + (size_t)mtile*128)*INNER;
    const __nv_bfloat16* Kg = g_K + ((size_t)z*Sdim + (size_t)ntile*128)*INNER;
    #pragma unroll
    for (int i=0;i<4;i++){
        int t = tid + i*256;
        int row = t >> 3, ch = (t & 7) << 3;
        cp16(Qs + row*QK2STR + ch, Qg + row*INNER + ch);
        cp16(Ks + row*QK2STR + ch, Kg + row*INNER + ch);
    }
    cp_commit();
    cp_wait<0>();
    __syncthreads();

    const int lane = tid & 31, warp = tid >> 5;
    const int g = lane >> 2, tg = lane & 3;
    const int wm = warp >> 1, wn = warp & 1;
    const int l7   = lane & 7;
    const int selA_r = ((lane >> 3) & 1) * 8;
    const int selA_c = (lane >> 4) * 8;
    const int selB_r = (lane >> 4) * 8;
    const int selB_c = ((lane >> 3) & 1) * 8;
    const uint32_t qbase = sbase;
    const uint32_t kbase = sbase + (128*QK2STR)*2;

    float acc[2][8][4];
    #pragma unroll
    for (int a=0;a<2;a++)
        #pragma unroll
        for (int bq=0;bq<8;bq++)
            #pragma unroll
            for (int k=0;k<4;k++) acc[a][bq][k]=0.f;

    #pragma unroll
    for (int kk=0; kk<4; kk++){
        const int k0 = kk*16;
        uint32_t af[2][4], bf[8][2];
        #pragma unroll
        for (int mt=0; mt<2; mt++){
            int row = wm*32 + mt*16 + selA_r + l7;
            ldsm_x4(af[mt], qbase + (row*QK2STR + k0 + selA_c)*2);
        }
        #pragma unroll
        for (int ntp=0; ntp<4; ntp++){
            int row = wn*64 + ntp*16 + selB_r + l7;
            uint32_t q[4];
            ldsm_x4(q, kbase + (row*QK2STR + k0 + selB_c)*2);
            bf[2*ntp  ][0] = q[0]; bf[2*ntp  ][1] = q[1];
            bf[2*ntp+1][0] = q[2]; bf[2*ntp+1][1] = q[3];
        }
        #pragma unroll
        for (int mt=0; mt<2; mt++)
            #pragma unroll
            for (int nt=0; nt<8; nt++)
                mma_bf16(acc[mt][nt], af[mt], bf[nt]);
    }

    #pragma unroll
    for (int mt=0; mt<2; mt++){
        #pragma unroll
        for (int nt=0; nt<8; nt++){
            const int n_loc = wn*64 + nt*8 + 2*tg;
            const int n = ntile*128 + n_loc;
            const float p0 = pad_s[n_loc], p1 = pad_s[n_loc+1];
            #pragma unroll
            for (int p=0; p<2; p++){
                const int m = mtile*128 + wm*32 + mt*16 + g + p*8;
                float v0 = acc[mt][nt][2*p]   * p0 - (1.0f - p0)*NEGC - ((n   < m) ? NEGC : 0.0f);
                float v1 = acc[mt][nt][2*p+1] * p1 - (1.0f - p1)*NEGC - ((n+1 < m) ? NEGC : 0.0f);
                stg_cs_f2(outb + ((size_t)m << 10) + n, v0*0.125f, v1*0.125f);
            }
        }
    }
}

// ---------------------------------------------------------------------------
extern "C" void kernel_launch(void* const* d_in, const int* in_sizes, int n_in,
                              void* d_out, int out_size)
{
    const float* X    = (const float*)d_in[0];
    const float* W    = (const float*)d_in[1];
    const float* bias = (const float*)d_in[2];
    const float* tok  = (const float*)d_in[3];
    float* out = (float*)d_out;

    cudaFuncSetAttribute(gemm1_rope_kernel,
        cudaFuncAttributeMaxDynamicSharedMemorySize, SMEM_A_BYTES);
    cudaFuncSetAttribute(attn_logits_kernel,
        cudaFuncAttributeMaxDynamicSharedMemorySize, SMEM_B_BYTES);

    sincos_kernel<<<64, 512>>>();
    prep_x_kernel<<<512, 256>>>(X);
    prep_w_kernel<<<dim3(64, 32), dim3(32, 8)>>>(W);
    gemm1_rope_kernel<<<dim3(16, 32), 128, SMEM_A_BYTES>>>(bias);
    attn_logits_kernel<<<dim3(8, 8, 64), 256, SMEM_B_BYTES>>>(tok, out);
}

// round 9
// speedup vs baseline: 1.4990x; 1.0383x over previous
#include <cuda_runtime.h>
#include <cuda_bf16.h>
#include <cstdint>

#define Bdim  4
#define Sdim  1024
#define Hdim  1024
#define ENTn  16
#define INNER 64
#define NOUT  2048
#define NEGC  1.0e12f

// Scratch (allocation-free rule: __device__ globals)
__device__ __nv_bfloat16 g_Q[Bdim*ENTn*Sdim*INNER];   // [b][h][s][d] bf16
__device__ __nv_bfloat16 g_K[Bdim*ENTn*Sdim*INNER];
__device__ __nv_bfloat16 g_Xbf[Bdim*Sdim*Hdim];       // X in bf16 [m][k]
__device__ __nv_bfloat16 g_Wt[NOUT*Hdim];             // W^T in bf16 [n][k]
__device__ float g_sin[Sdim*(INNER/2)];               // [s][j]
__device__ float g_cos[Sdim*(INNER/2)];

__device__ __forceinline__ void cp16(void* s, const void* g){
    uint32_t sa = (uint32_t)__cvta_generic_to_shared(s);
    asm volatile("cp.async.cg.shared.global [%0], [%1], 16;" :: "r"(sa), "l"(g));
}
__device__ __forceinline__ void cp_commit(){ asm volatile("cp.async.commit_group;" ::: "memory"); }
template<int N> __device__ __forceinline__ void cp_wait(){
    asm volatile("cp.async.wait_group %0;" :: "n"(N) : "memory");
}
__device__ __forceinline__ void ldsm_x4(uint32_t* r, uint32_t addr){
    asm volatile("ldmatrix.sync.aligned.m8n8.x4.shared.b16 {%0,%1,%2,%3}, [%4];"
        : "=r"(r[0]), "=r"(r[1]), "=r"(r[2]), "=r"(r[3]) : "r"(addr));
}
__device__ __forceinline__ void mma_bf16(float* c, const uint32_t* a, const uint32_t* b){
    asm volatile("mma.sync.aligned.m16n8k16.row.col.f32.bf16.bf16.f32 "
        "{%0,%1,%2,%3}, {%4,%5,%6,%7}, {%8,%9}, {%0,%1,%2,%3};"
        : "+f"(c[0]), "+f"(c[1]), "+f"(c[2]), "+f"(c[3])
        : "r"(a[0]), "r"(a[1]), "r"(a[2]), "r"(a[3]), "r"(b[0]), "r"(b[1]));
}
__device__ __forceinline__ void stg_cs_f2(float* p, float x, float y){
    asm volatile("st.global.cs.v2.f32 [%0], {%1,%2};" :: "l"(p), "f"(x), "f"(y) : "memory");
}
__device__ __forceinline__ void stg_cs_f4(float* p, float4 v){
    asm volatile("st.global.cs.v4.f32 [%0], {%1,%2,%3,%4};"
        :: "l"(p), "f"(v.x), "f"(v.y), "f"(v.z), "f"(v.w) : "memory");
}

// ---------------------------------------------------------------------------
// Kernel T: RoPE sin/cos table (exact fp32 math matching jax reference)
// ---------------------------------------------------------------------------
__global__ void sincos_kernel(){
    int idx = blockIdx.x*blockDim.x + threadIdx.x;
    if (idx >= Sdim*32) return;
    int s = idx >> 5, j = idx & 31;
    float freq = powf(10000.0f, -(float)j * 0.03125f);
    float ang  = (float)s * freq;
    g_sin[idx] = sinf(ang);
    g_cos[idx] = cosf(ang);
}

// ---------------------------------------------------------------------------
// Prep: X (f32) -> g_Xbf (bf16)
// ---------------------------------------------------------------------------
__global__ void prep_x_kernel(const float* __restrict__ X){
    int n2 = Bdim*Sdim*Hdim/2;
    for (int i = blockIdx.x*blockDim.x + threadIdx.x; i < n2; i += gridDim.x*blockDim.x){
        float2 v = reinterpret_cast<const float2*>(X)[i];
        __nv_bfloat162 o;
        o.x = __float2bfloat16_rn(v.x);
        o.y = __float2bfloat16_rn(v.y);
        reinterpret_cast<__nv_bfloat162*>(g_Xbf)[i] = o;
    }
}

// ---------------------------------------------------------------------------
// Prep: W [k][n] f32 -> g_Wt [n][k] bf16 (tiled transpose)
// ---------------------------------------------------------------------------
__global__ void prep_w_kernel(const float* __restrict__ W){
    __shared__ float t[32][33];
    const int k0 = blockIdx.y*32, n0 = blockIdx.x*32;
    #pragma unroll
    for (int i = threadIdx.y; i < 32; i += 8)
        t[i][threadIdx.x] = W[(size_t)(k0+i)*NOUT + n0 + threadIdx.x];
    __syncthreads();
    #pragma unroll
    for (int i = threadIdx.y; i < 32; i += 8)
        g_Wt[(size_t)(n0+i)*Hdim + k0 + threadIdx.x] = __float2bfloat16_rn(t[threadIdx.x][i]);
}

// ---------------------------------------------------------------------------
// Kernel A: C = X@W + b, fused interleaved RoPE, scatter to g_Q/g_K (bf16).
// M=4096, N=2048, K=1024. CTA tile 128x128, 512 threads, 16 warps in 4x4,
// warp tile 32x32 (acc=32 regs -> 2 CTAs/SM = 32 warps/SM, occ 50%).
// BK=64 halves, double-buffered cp.async, stride 72 halves (conflict-free
// LDSM, 16B aligned).
// ---------------------------------------------------------------------------
#define G1STR 72
#define SMEM_A_BYTES (4*128*G1STR*2)   // A[2] + B[2] buffers, 73728 B

__global__ void __launch_bounds__(512, 2) gemm1_rope_kernel(
    const float* __restrict__ bias)
{
    extern __shared__ __nv_bfloat16 smb[];
    const uint32_t sbase = (uint32_t)__cvta_generic_to_shared(smb);
    const int tid  = threadIdx.x;
    const int lane = tid & 31, warp = tid >> 5;
    const int g = lane >> 2, tg = lane & 3;
    const int wm = warp >> 2, wn = warp & 3;          // 4x4 warps, 32x32 tiles
    const int mtile = blockIdx.y, ntile = blockIdx.x; // grid (16, 32)
    const __nv_bfloat16* Xb = g_Xbf + (size_t)mtile*128*Hdim;
    const __nv_bfloat16* Wb = g_Wt  + (size_t)ntile*128*Hdim;

    const int l7   = lane & 7;
    const int selA_r = ((lane >> 3) & 1) * 8;
    const int selA_c = (lane >> 4) * 8;
    const int selB_r = (lane >> 4) * 8;
    const int selB_c = ((lane >> 3) & 1) * 8;

    float acc[2][4][4];
    #pragma unroll
    for (int a=0;a<2;a++)
        #pragma unroll
        for (int bq=0;bq<4;bq++)
            #pragma unroll
            for (int k=0;k<4;k++) acc[a][bq][k]=0.f;

    auto load_stage = [&](int ks, int b){
        __nv_bfloat16* Ad = smb + b*128*G1STR;
        __nv_bfloat16* Bd = smb + (2+b)*128*G1STR;
        const __nv_bfloat16* xs = Xb + ks*64;
        const __nv_bfloat16* ws = Wb + ks*64;
        #pragma unroll
        for (int i=0;i<2;i++){
            int c = tid + i*512;                 // 0..1023
            int row = c >> 3, ch = (c & 7) << 3; // 128 rows x 8 chunks of 8 halves
            cp16(Ad + row*G1STR + ch, xs + (size_t)row*Hdim + ch);
            cp16(Bd + row*G1STR + ch, ws + (size_t)row*Hdim + ch);
        }
        cp_commit();
    };

    load_stage(0, 0);
    int buf = 0;
    for (int ks = 0; ks < 16; ks++){
        if (ks < 15){ load_stage(ks+1, buf^1); cp_wait<1>(); }
        else        { cp_wait<0>(); }
        __syncthreads();
        const uint32_t abase = sbase + (buf*128*G1STR)*2;
        const uint32_t bbase = sbase + ((2+buf)*128*G1STR)*2;
        #pragma unroll
        for (int kk=0; kk<4; kk++){
            const int k0 = kk*16;
            uint32_t af[2][4], bf[4][2];
            #pragma unroll
            for (int mt=0; mt<2; mt++){
                int row = wm*32 + mt*16 + selA_r + l7;
                ldsm_x4(af[mt], abase + (row*G1STR + k0 + selA_c)*2);
            }
            #pragma unroll
            for (int ntp=0; ntp<2; ntp++){
                int row = wn*32 + ntp*16 + selB_r + l7;
                uint32_t q[4];
                ldsm_x4(q, bbase + (row*G1STR + k0 + selB_c)*2);
                bf[2*ntp  ][0] = q[0]; bf[2*ntp  ][1] = q[1];
                bf[2*ntp+1][0] = q[2]; bf[2*ntp+1][1] = q[3];
            }
            #pragma unroll
            for (int mt=0; mt<2; mt++)
                #pragma unroll
                for (int nt=0; nt<4; nt++)
                    mma_bf16(acc[mt][nt], af[mt], bf[nt]);
        }
        __syncthreads();
        buf ^= 1;
    }

    // Epilogue: bias + RoPE (interleaved pair == c0/c1 accumulator pair), bf16 out
    #pragma unroll
    for (int nt=0; nt<4; nt++){
        const int n_loc = wn*32 + nt*8 + 2*tg;
        const int c = ntile*128 + n_loc;         // even
        const int h = c >> 7, r = c & 127;
        const int d = r & 63, jj = d >> 1;
        __nv_bfloat16* dst = (r < 64) ? g_Q : g_K;
        const float b0 = bias[c], b1 = bias[c+1];
        #pragma unroll
        for (int mt=0; mt<2; mt++){
            #pragma unroll
            for (int p=0; p<2; p++){
                int m = mtile*128 + wm*32 + mt*16 + g + p*8;
                int bb = m >> 10, s = m & 1023;
                float sv = g_sin[s*32 + jj], cv = g_cos[s*32 + jj];
                float v0 = acc[mt][nt][2*p]   + b0;
                float v1 = acc[mt][nt][2*p+1] + b1;
                __nv_bfloat162 o;
                o.x = __float2bfloat16_rn(v0*cv - v1*sv);
                o.y = __float2bfloat16_rn(v1*cv + v0*sv);
                int idx = ((bb*ENTn + h)*Sdim + s)*INNER + d;
                *reinterpret_cast<__nv_bfloat162*>(dst + idx) = o;
            }
        }
    }
}

// ---------------------------------------------------------------------------
// Kernel B: logits[z=(b,h)][m][n] = (Q[m]·K[n]) masked/scaled. 128x128 tiles.
// Strictly-lower tiles: exact constant, streaming float4 stores.
// Upper/diagonal: bf16 m16n8k16 over d=64, ldmatrix fragment loads,
// streaming (st.global.cs) output stores.
// ---------------------------------------------------------------------------
#define QK2STR 72
#define SMEM_B_BYTES (2*128*QK2STR*2)

__global__ void __launch_bounds__(256) attn_logits_kernel(
    const float* __restrict__ tok, float* __restrict__ out)
{
    const int ntile = blockIdx.x, mtile = blockIdx.y, z = blockIdx.z;
    const int bidx = z >> 4;
    const int tid = threadIdx.x;
    float* outb = out + ((size_t)z << 20);
    const float* padp = tok + bidx*Sdim + ntile*128;

    if (ntile < mtile){
        const int n4 = (tid & 31) << 2;
        const int m0 = mtile*128 + (tid >> 5);
        float4 pv = *reinterpret_cast<const float4*>(padp + n4);
        float4 val;
        val.x = (-(1.0f - pv.x)*NEGC - NEGC)*0.125f;
        val.y = (-(1.0f - pv.y)*NEGC - NEGC)*0.125f;
        val.z = (-(1.0f - pv.z)*NEGC - NEGC)*0.125f;
        val.w = (-(1.0f - pv.w)*NEGC - NEGC)*0.125f;
        const int ncol = ntile*128 + n4;
        #pragma unroll
        for (int i=0;i<16;i++)
            stg_cs_f4(outb + ((size_t)(m0 + i*8) << 10) + ncol, val);
        return;
    }

    extern __shared__ __nv_bfloat16 smb[];
    const uint32_t sbase = (uint32_t)__cvta_generic_to_shared(smb);
    __nv_bfloat16* Qs = smb;                 // [128][QK2STR]
    __nv_bfloat16* Ks = smb + 128*QK2STR;
    __shared__ float pad_s[128];
    if (tid < 128) pad_s[tid] = padp[tid];

    const __nv_bfloat16* Qg = g_Q + ((size_t)z*Sdim + (size_t)mtile*128)*INNER;
    const __nv_bfloat16* Kg = g_K + ((size_t)z*Sdim + (size_t)ntile*128)*INNER;
    #pragma unroll
    for (int i=0;i<4;i++){
        int t = tid + i*256;
        int row = t >> 3, ch = (t & 7) << 3;
        cp16(Qs + row*QK2STR + ch, Qg + row*INNER + ch);
        cp16(Ks + row*QK2STR + ch, Kg + row*INNER + ch);
    }
    cp_commit();
    cp_wait<0>();
    __syncthreads();

    const int lane = tid & 31, warp = tid >> 5;
    const int g = lane >> 2, tg = lane & 3;
    const int wm = warp >> 1, wn = warp & 1;
    const int l7   = lane & 7;
    const int selA_r = ((lane >> 3) & 1) * 8;
    const int selA_c = (lane >> 4) * 8;
    const int selB_r = (lane >> 4) * 8;
    const int selB_c = ((lane >> 3) & 1) * 8;
    const uint32_t qbase = sbase;
    const uint32_t kbase = sbase + (128*QK2STR)*2;

    float acc[2][8][4];
    #pragma unroll
    for (int a=0;a<2;a++)
        #pragma unroll
        for (int bq=0;bq<8;bq++)
            #pragma unroll
            for (int k=0;k<4;k++) acc[a][bq][k]=0.f;

    #pragma unroll
    for (int kk=0; kk<4; kk++){
        const int k0 = kk*16;
        uint32_t af[2][4], bf[8][2];
        #pragma unroll
        for (int mt=0; mt<2; mt++){
            int row = wm*32 + mt*16 + selA_r + l7;
            ldsm_x4(af[mt], qbase + (row*QK2STR + k0 + selA_c)*2);
        }
        #pragma unroll
        for (int ntp=0; ntp<4; ntp++){
            int row = wn*64 + ntp*16 + selB_r + l7;
            uint32_t q[4];
            ldsm_x4(q, kbase + (row*QK2STR + k0 + selB_c)*2);
            bf[2*ntp  ][0] = q[0]; bf[2*ntp  ][1] = q[1];
            bf[2*ntp+1][0] = q[2]; bf[2*ntp+1][1] = q[3];
        }
        #pragma unroll
        for (int mt=0; mt<2; mt++)
            #pragma unroll
            for (int nt=0; nt<8; nt++)
                mma_bf16(acc[mt][nt], af[mt], bf[nt]);
    }

    #pragma unroll
    for (int mt=0; mt<2; mt++){
        #pragma unroll
        for (int nt=0; nt<8; nt++){
            const int n_loc = wn*64 + nt*8 + 2*tg;
            const int n = ntile*128 + n_loc;
            const float p0 = pad_s[n_loc], p1 = pad_s[n_loc+1];
            #pragma unroll
            for (int p=0; p<2; p++){
                const int m = mtile*128 + wm*32 + mt*16 + g + p*8;
                float v0 = acc[mt][nt][2*p]   * p0 - (1.0f - p0)*NEGC - ((n   < m) ? NEGC : 0.0f);
                float v1 = acc[mt][nt][2*p+1] * p1 - (1.0f - p1)*NEGC - ((n+1 < m) ? NEGC : 0.0f);
                stg_cs_f2(outb + ((size_t)m << 10) + n, v0*0.125f, v1*0.125f);
            }
        }
    }
}

// ---------------------------------------------------------------------------
extern "C" void kernel_launch(void* const* d_in, const int* in_sizes, int n_in,
                              void* d_out, int out_size)
{
    const float* X    = (const float*)d_in[0];
    const float* W    = (const float*)d_in[1];
    const float* bias = (const float*)d_in[2];
    const float* tok  = (const float*)d_in[3];
    float* out = (float*)d_out;

    cudaFuncSetAttribute(gemm1_rope_kernel,
        cudaFuncAttributeMaxDynamicSharedMemorySize, SMEM_A_BYTES);
    cudaFuncSetAttribute(attn_logits_kernel,
        cudaFuncAttributeMaxDynamicSharedMemorySize, SMEM_B_BYTES);

    sincos_kernel<<<64, 512>>>();
    prep_x_kernel<<<512, 256>>>(X);
    prep_w_kernel<<<dim3(64, 32), dim3(32, 8)>>>(W);
    gemm1_rope_kernel<<<dim3(16, 32), 512, SMEM_A_BYTES>>>(bias);
    attn_logits_kernel<<<dim3(8, 8, 64), 256, SMEM_B_BYTES>>>(tok, out);
}

// round 10
// speedup vs baseline: 1.5624x; 1.0423x over previous
#include <cuda_runtime.h>
#include <cuda_fp16.h>
#include <cstdint>

#define Bdim  4
#define Sdim  1024
#define Hdim  1024
#define ENTn  16
#define INNER 64
#define NOUT  2048
#define NEGC  1.0e12f

// Scratch (allocation-free rule: __device__ globals)
__device__ __half g_Q[Bdim*ENTn*Sdim*INNER];   // [b][h][s][d] f16
__device__ __half g_K[Bdim*ENTn*Sdim*INNER];
__device__ __half g_Xh[Bdim*Sdim*Hdim];        // X in f16 [m][k]
__device__ __half g_Wt[NOUT*Hdim];             // W^T in f16 [n][k]
__device__ float g_sin[Sdim*(INNER/2)];        // [s][j]
__device__ float g_cos[Sdim*(INNER/2)];

__device__ __forceinline__ void cp16(void* s, const void* g){
    uint32_t sa = (uint32_t)__cvta_generic_to_shared(s);
    asm volatile("cp.async.cg.shared.global [%0], [%1], 16;" :: "r"(sa), "l"(g));
}
__device__ __forceinline__ void cp_commit(){ asm volatile("cp.async.commit_group;" ::: "memory"); }
template<int N> __device__ __forceinline__ void cp_wait(){
    asm volatile("cp.async.wait_group %0;" :: "n"(N) : "memory");
}
__device__ __forceinline__ void ldsm_x4(uint32_t* r, uint32_t addr){
    asm volatile("ldmatrix.sync.aligned.m8n8.x4.shared.b16 {%0,%1,%2,%3}, [%4];"
        : "=r"(r[0]), "=r"(r[1]), "=r"(r[2]), "=r"(r[3]) : "r"(addr));
}
// f16 inputs, f16 accumulators (2 C regs) — 2x legacy rate, half the regs
__device__ __forceinline__ void mma_f16acc(uint32_t* c, const uint32_t* a, const uint32_t* b){
    asm volatile("mma.sync.aligned.m16n8k16.row.col.f16.f16.f16.f16 "
        "{%0,%1}, {%2,%3,%4,%5}, {%6,%7}, {%0,%1};"
        : "+r"(c[0]), "+r"(c[1])
        : "r"(a[0]), "r"(a[1]), "r"(a[2]), "r"(a[3]), "r"(b[0]), "r"(b[1]));
}
// f16 inputs, f32 accumulators (attn)
__device__ __forceinline__ void mma_f32acc(float* c, const uint32_t* a, const uint32_t* b){
    asm volatile("mma.sync.aligned.m16n8k16.row.col.f32.f16.f16.f32 "
        "{%0,%1,%2,%3}, {%4,%5,%6,%7}, {%8,%9}, {%0,%1,%2,%3};"
        : "+f"(c[0]), "+f"(c[1]), "+f"(c[2]), "+f"(c[3])
        : "r"(a[0]), "r"(a[1]), "r"(a[2]), "r"(a[3]), "r"(b[0]), "r"(b[1]));
}
__device__ __forceinline__ void stg_cs_f2(float* p, float x, float y){
    asm volatile("st.global.cs.v2.f32 [%0], {%1,%2};" :: "l"(p), "f"(x), "f"(y) : "memory");
}
__device__ __forceinline__ void stg_cs_f4(float* p, float4 v){
    asm volatile("st.global.cs.v4.f32 [%0], {%1,%2,%3,%4};"
        :: "l"(p), "f"(v.x), "f"(v.y), "f"(v.z), "f"(v.w) : "memory");
}

// ---------------------------------------------------------------------------
// Kernel T: RoPE sin/cos table (exact fp32 math matching jax reference)
// ---------------------------------------------------------------------------
__global__ void sincos_kernel(){
    int idx = blockIdx.x*blockDim.x + threadIdx.x;
    if (idx >= Sdim*32) return;
    int s = idx >> 5, j = idx & 31;
    float freq = powf(10000.0f, -(float)j * 0.03125f);
    float ang  = (float)s * freq;
    g_sin[idx] = sinf(ang);
    g_cos[idx] = cosf(ang);
}

// ---------------------------------------------------------------------------
// Prep: X (f32) -> g_Xh (f16)
// ---------------------------------------------------------------------------
__global__ void prep_x_kernel(const float* __restrict__ X){
    int n2 = Bdim*Sdim*Hdim/2;
    for (int i = blockIdx.x*blockDim.x + threadIdx.x; i < n2; i += gridDim.x*blockDim.x){
        float2 v = reinterpret_cast<const float2*>(X)[i];
        __half2 o;
        o.x = __float2half_rn(v.x);
        o.y = __float2half_rn(v.y);
        reinterpret_cast<__half2*>(g_Xh)[i] = o;
    }
}

// ---------------------------------------------------------------------------
// Prep: W [k][n] f32 -> g_Wt [n][k] f16 (tiled transpose)
// ---------------------------------------------------------------------------
__global__ void prep_w_kernel(const float* __restrict__ W){
    __shared__ float t[32][33];
    const int k0 = blockIdx.y*32, n0 = blockIdx.x*32;
    #pragma unroll
    for (int i = threadIdx.y; i < 32; i += 8)
        t[i][threadIdx.x] = W[(size_t)(k0+i)*NOUT + n0 + threadIdx.x];
    __syncthreads();
    #pragma unroll
    for (int i = threadIdx.y; i < 32; i += 8)
        g_Wt[(size_t)(n0+i)*Hdim + k0 + threadIdx.x] = __float2half_rn(t[threadIdx.x][i]);
}

// ---------------------------------------------------------------------------
// Kernel A: C = X@W + b, fused interleaved RoPE, scatter to g_Q/g_K (f16).
// M=4096, N=2048, K=1024. CTA tile 128x128, 4 warps (2x2), warp tile 64x64,
// f16 accumulators. BK=32 halves, double-buffered cp.async, stride 40 halves
// (quad-bank 5r mod 8 bijective -> LDSM conflict-free, 16B aligned).
// 40KB smem -> 4 CTAs/SM (16 warps/SM), grid 512 fits one wave.
// Per kk-step: 8 LDSM.x4 -> 32 HMMA (ratio 4), smem 48KB/k-block (0.59x R9).
// ---------------------------------------------------------------------------
#define G1STR 40
#define SMEM_A_BYTES (4*128*G1STR*2)   // A[2] + B[2] buffers, 40960 B

__global__ void __launch_bounds__(128, 4) gemm1_rope_kernel(
    const float* __restrict__ bias)
{
    extern __shared__ __half smb[];
    const uint32_t sbase = (uint32_t)__cvta_generic_to_shared(smb);
    const int tid  = threadIdx.x;
    const int lane = tid & 31, warp = tid >> 5;
    const int g = lane >> 2, tg = lane & 3;
    const int wm = warp >> 1, wn = warp & 1;          // 2x2 warps, 64x64 tiles
    const int mtile = blockIdx.y, ntile = blockIdx.x; // grid (16, 32)
    const __half* Xb = g_Xh + (size_t)mtile*128*Hdim;
    const __half* Wb = g_Wt + (size_t)ntile*128*Hdim;

    const int l7   = lane & 7;
    const int selA_r = ((lane >> 3) & 1) * 8;
    const int selA_c = (lane >> 4) * 8;
    const int selB_r = (lane >> 4) * 8;
    const int selB_c = ((lane >> 3) & 1) * 8;

    uint32_t acc[4][8][2];                            // f16x2 accumulators
    #pragma unroll
    for (int a=0;a<4;a++)
        #pragma unroll
        for (int bq=0;bq<8;bq++){ acc[a][bq][0]=0u; acc[a][bq][1]=0u; }

    auto load_stage = [&](int ks, int b){
        __half* Ad = smb + b*128*G1STR;
        __half* Bd = smb + (2+b)*128*G1STR;
        const __half* xs = Xb + ks*32;
        const __half* ws = Wb + ks*32;
        #pragma unroll
        for (int i=0;i<4;i++){
            int c = tid + i*128;                 // 0..511
            int row = c >> 2, ch = (c & 3) << 3; // 128 rows x 4 chunks of 8 halves
            cp16(Ad + row*G1STR + ch, xs + (size_t)row*Hdim + ch);
            cp16(Bd + row*G1STR + ch, ws + (size_t)row*Hdim + ch);
        }
        cp_commit();
    };

    load_stage(0, 0);
    int buf = 0;
    for (int ks = 0; ks < 32; ks++){
        if (ks < 31){ load_stage(ks+1, buf^1); cp_wait<1>(); }
        else        { cp_wait<0>(); }
        __syncthreads();
        const uint32_t abase = sbase + (buf*128*G1STR)*2;
        const uint32_t bbase = sbase + ((2+buf)*128*G1STR)*2;
        #pragma unroll
        for (int kk=0; kk<2; kk++){
            const int k0 = kk*16;
            uint32_t af[4][4], bf[8][2];
            #pragma unroll
            for (int mt=0; mt<4; mt++){
                int row = wm*64 + mt*16 + selA_r + l7;
                ldsm_x4(af[mt], abase + (row*G1STR + k0 + selA_c)*2);
            }
            #pragma unroll
            for (int ntp=0; ntp<4; ntp++){
                int row = wn*64 + ntp*16 + selB_r + l7;
                uint32_t q[4];
                ldsm_x4(q, bbase + (row*G1STR + k0 + selB_c)*2);
                bf[2*ntp  ][0] = q[0]; bf[2*ntp  ][1] = q[1];
                bf[2*ntp+1][0] = q[2]; bf[2*ntp+1][1] = q[3];
            }
            #pragma unroll
            for (int mt=0; mt<4; mt++)
                #pragma unroll
                for (int nt=0; nt<8; nt++)
                    mma_f16acc(acc[mt][nt], af[mt], bf[nt]);
        }
        __syncthreads();
        buf ^= 1;
    }

    // Epilogue: bias + RoPE (interleaved pair == packed half2 lanes), f16 out
    #pragma unroll
    for (int nt=0; nt<8; nt++){
        const int n_loc = wn*64 + nt*8 + 2*tg;
        const int c = ntile*128 + n_loc;         // even
        const int h = c >> 7, r = c & 127;
        const int d = r & 63, jj = d >> 1;
        __half* dst = (r < 64) ? g_Q : g_K;
        const float b0 = bias[c], b1 = bias[c+1];
        #pragma unroll
        for (int mt=0; mt<4; mt++){
            #pragma unroll
            for (int p=0; p<2; p++){
                int m = mtile*128 + wm*64 + mt*16 + g + p*8;
                int bb = m >> 10, s = m & 1023;
                float sv = g_sin[s*32 + jj], cv = g_cos[s*32 + jj];
                __half2 hv = *reinterpret_cast<__half2*>(&acc[mt][nt][p]);
                float v0 = __half2float(hv.x) + b0;
                float v1 = __half2float(hv.y) + b1;
                __half2 o;
                o.x = __float2half_rn(v0*cv - v1*sv);
                o.y = __float2half_rn(v1*cv + v0*sv);
                int idx = ((bb*ENTn + h)*Sdim + s)*INNER + d;
                *reinterpret_cast<__half2*>(dst + idx) = o;
            }
        }
    }
}

// ---------------------------------------------------------------------------
// Kernel B: logits[z=(b,h)][m][n] = (Q[m]·K[n]) masked/scaled. 128x128 tiles.
// Strictly-lower tiles: exact constant, streaming float4 stores.
// Upper/diagonal: f16 m16n8k16 (f32 acc) over d=64, ldmatrix fragment loads,
// streaming (st.global.cs) output stores.
// ---------------------------------------------------------------------------
#define QK2STR 72
#define SMEM_B_BYTES (2*128*QK2STR*2)

__global__ void __launch_bounds__(256) attn_logits_kernel(
    const float* __restrict__ tok, float* __restrict__ out)
{
    const int ntile = blockIdx.x, mtile = blockIdx.y, z = blockIdx.z;
    const int bidx = z >> 4;
    const int tid = threadIdx.x;
    float* outb = out + ((size_t)z << 20);
    const float* padp = tok + bidx*Sdim + ntile*128;

    if (ntile < mtile){
        const int n4 = (tid & 31) << 2;
        const int m0 = mtile*128 + (tid >> 5);
        float4 pv = *reinterpret_cast<const float4*>(padp + n4);
        float4 val;
        val.x = (-(1.0f - pv.x)*NEGC - NEGC)*0.125f;
        val.y = (-(1.0f - pv.y)*NEGC - NEGC)*0.125f;
        val.z = (-(1.0f - pv.z)*NEGC - NEGC)*0.125f;
        val.w = (-(1.0f - pv.w)*NEGC - NEGC)*0.125f;
        const int ncol = ntile*128 + n4;
        #pragma unroll
        for (int i=0;i<16;i++)
            stg_cs_f4(outb + ((size_t)(m0 + i*8) << 10) + ncol, val);
        return;
    }

    extern __shared__ __half smh[];
    const uint32_t sbase = (uint32_t)__cvta_generic_to_shared(smh);
    __half* Qs = smh;                 // [128][QK2STR]
    __half* Ks = smh + 128*QK2STR;
    __shared__ float pad_s[128];
    if (tid < 128) pad_s[tid] = padp[tid];

    const __half* Qg = g_Q + ((size_t)z*Sdim + (size_t)mtile*128)*INNER;
    const __half* Kg = g_K + ((size_t)z*Sdim + (size_t)ntile*128)*INNER;
    #pragma unroll
    for (int i=0;i<4;i++){
        int t = tid + i*256;
        int row = t >> 3, ch = (t & 7) << 3;
        cp16(Qs + row*QK2STR + ch, Qg + row*INNER + ch);
        cp16(Ks + row*QK2STR + ch, Kg + row*INNER + ch);
    }
    cp_commit();
    cp_wait<0>();
    __syncthreads();

    const int lane = tid & 31, warp = tid >> 5;
    const int g = lane >> 2, tg = lane & 3;
    const int wm = warp >> 1, wn = warp & 1;
    const int l7   = lane & 7;
    const int selA_r = ((lane >> 3) & 1) * 8;
    const int selA_c = (lane >> 4) * 8;
    const int selB_r = (lane >> 4) * 8;
    const int selB_c = ((lane >> 3) & 1) * 8;
    const uint32_t qbase = sbase;
    const uint32_t kbase = sbase + (128*QK2STR)*2;

    float acc[2][8][4];
    #pragma unroll
    for (int a=0;a<2;a++)
        #pragma unroll
        for (int bq=0;bq<8;bq++)
            #pragma unroll
            for (int k=0;k<4;k++) acc[a][bq][k]=0.f;

    #pragma unroll
    for (int kk=0; kk<4; kk++){
        const int k0 = kk*16;
        uint32_t af[2][4], bf[8][2];
        #pragma unroll
        for (int mt=0; mt<2; mt++){
            int row = wm*32 + mt*16 + selA_r + l7;
            ldsm_x4(af[mt], qbase + (row*QK2STR + k0 + selA_c)*2);
        }
        #pragma unroll
        for (int ntp=0; ntp<4; ntp++){
            int row = wn*64 + ntp*16 + selB_r + l7;
            uint32_t q[4];
            ldsm_x4(q, kbase + (row*QK2STR + k0 + selB_c)*2);
            bf[2*ntp  ][0] = q[0]; bf[2*ntp  ][1] = q[1];
            bf[2*ntp+1][0] = q[2]; bf[2*ntp+1][1] = q[3];
        }
        #pragma unroll
        for (int mt=0; mt<2; mt++)
            #pragma unroll
            for (int nt=0; nt<8; nt++)
                mma_f32acc(acc[mt][nt], af[mt], bf[nt]);
    }

    #pragma unroll
    for (int mt=0; mt<2; mt++){
        #pragma unroll
        for (int nt=0; nt<8; nt++){
            const int n_loc = wn*64 + nt*8 + 2*tg;
            const int n = ntile*128 + n_loc;
            const float p0 = pad_s[n_loc], p1 = pad_s[n_loc+1];
            #pragma unroll
            for (int p=0; p<2; p++){
                const int m = mtile*128 + wm*32 + mt*16 + g + p*8;
                float v0 = acc[mt][nt][2*p]   * p0 - (1.0f - p0)*NEGC - ((n   < m) ? NEGC : 0.0f);
                float v1 = acc[mt][nt][2*p+1] * p1 - (1.0f - p1)*NEGC - ((n+1 < m) ? NEGC : 0.0f);
                stg_cs_f2(outb + ((size_t)m << 10) + n, v0*0.125f, v1*0.125f);
            }
        }
    }
}

// ---------------------------------------------------------------------------
extern "C" void kernel_launch(void* const* d_in, const int* in_sizes, int n_in,
                              void* d_out, int out_size)
{
    const float* X    = (const float*)d_in[0];
    const float* W    = (const float*)d_in[1];
    const float* bias = (const float*)d_in[2];
    const float* tok  = (const float*)d_in[3];
    float* out = (float*)d_out;

    cudaFuncSetAttribute(gemm1_rope_kernel,
        cudaFuncAttributeMaxDynamicSharedMemorySize, SMEM_A_BYTES);
    cudaFuncSetAttribute(attn_logits_kernel,
        cudaFuncAttributeMaxDynamicSharedMemorySize, SMEM_B_BYTES);

    sincos_kernel<<<64, 512>>>();
    prep_x_kernel<<<512, 256>>>(X);
    prep_w_kernel<<<dim3(64, 32), dim3(32, 8)>>>(W);
    gemm1_rope_kernel<<<dim3(16, 32), 128, SMEM_A_BYTES>>>(bias);
    attn_logits_kernel<<<dim3(8, 8, 64), 256, SMEM_B_BYTES>>>(tok, out);
}